// round 1
// baseline (speedup 1.0000x reference)
#include <cuda_runtime.h>
#include <cuda_bf16.h>
#include <cstdint>

#define N_PIX 4096
#define C_IN  256
#define DQK   32
#define B_SZ  4
#define PSTR  68   // sP row stride (64 + 4 pad), keeps 16B alignment

// ---------------- device scratch (no allocations allowed) ----------------
__device__ __align__(16) float g_Q[B_SZ * DQK * N_PIX];     // [b][d][n]
__device__ __align__(16) float g_K[B_SZ * DQK * N_PIX];     // [b][d][n]
__device__ __align__(16) float g_V[B_SZ * N_PIX * C_IN];    // [b][n][c]
__device__ __align__(16) float g_Wf[320 * C_IN];            // folded weights: rows 0-31 Q, 32-63 K, 64-319 V
__device__ __align__(16) float g_Bf[320];                   // folded biases

// ---------------- fold BN into 1x1-conv weights ----------------
__global__ void fold_kernel(
    const float* __restrict__ qw, const float* __restrict__ qb,
    const float* __restrict__ qg, const float* __restrict__ qbe,
    const float* __restrict__ qm, const float* __restrict__ qv,
    const float* __restrict__ kw, const float* __restrict__ kb,
    const float* __restrict__ kg, const float* __restrict__ kbe,
    const float* __restrict__ km, const float* __restrict__ kv,
    const float* __restrict__ vw, const float* __restrict__ vb,
    const float* __restrict__ vg, const float* __restrict__ vbe,
    const float* __restrict__ vm, const float* __restrict__ vv)
{
    int r = blockIdx.x;
    const float *w, *bb, *g, *be, *mn, *vr; int j;
    if (r < 32)      { w = qw; bb = qb; g = qg; be = qbe; mn = qm; vr = qv; j = r; }
    else if (r < 64) { w = kw; bb = kb; g = kg; be = kbe; mn = km; vr = kv; j = r - 32; }
    else             { w = vw; bb = vb; g = vg; be = vbe; mn = vm; vr = vv; j = r - 64; }
    float inv = g[j] * rsqrtf(vr[j] + 1e-5f);
    int c = threadIdx.x;
    g_Wf[r * C_IN + c] = w[j * C_IN + c] * inv;
    if (c == 0) g_Bf[r] = bb[j] * inv + be[j] - mn[j] * inv;
}

// ---------------- projection: out_rows = Wf(seg) @ x  + Bf ----------------
// grid: (N_PIX/128, 10 segs, B).  seg 0 -> Q (x1), seg 1 -> K (x2), segs 2-9 -> V (x2)
__global__ __launch_bounds__(128) void proj_kernel(
    const float* __restrict__ x1, const float* __restrict__ x2)
{
    __shared__ float sW[32 * C_IN];
    __shared__ float sB[32];
    int seg = blockIdx.y, b = blockIdx.z;
    int tid = threadIdx.x;
    int n = blockIdx.x * 128 + tid;
    int r0 = seg * 32;
    for (int i = tid; i < 32 * C_IN; i += 128) sW[i] = g_Wf[r0 * C_IN + i];
    if (tid < 32) sB[tid] = g_Bf[r0 + tid];
    __syncthreads();

    const float* x  = (seg == 0) ? x1 : x2;
    const float* xb = x + (size_t)b * C_IN * N_PIX + n;

    float acc[32];
#pragma unroll
    for (int d = 0; d < 32; ++d) acc[d] = 0.f;

#pragma unroll 4
    for (int c = 0; c < C_IN; c += 4) {
        float xv0 = xb[(c + 0) * N_PIX];
        float xv1 = xb[(c + 1) * N_PIX];
        float xv2 = xb[(c + 2) * N_PIX];
        float xv3 = xb[(c + 3) * N_PIX];
#pragma unroll
        for (int d = 0; d < 32; ++d) {
            float4 w = *(const float4*)&sW[d * C_IN + c];
            acc[d] = fmaf(w.x, xv0, acc[d]);
            acc[d] = fmaf(w.y, xv1, acc[d]);
            acc[d] = fmaf(w.z, xv2, acc[d]);
            acc[d] = fmaf(w.w, xv3, acc[d]);
        }
    }

    if (seg < 2) {
        float* g  = (seg == 0) ? g_Q : g_K;
        float* gb = g + (size_t)b * DQK * N_PIX + n;
#pragma unroll
        for (int d = 0; d < 32; ++d) gb[d * N_PIX] = acc[d] + sB[d];
    } else {
        int c0 = (seg - 2) * 32;
        float* gb = g_V + ((size_t)b * N_PIX + n) * C_IN + c0;
#pragma unroll
        for (int d = 0; d < 32; ++d) gb[d] = acc[d] + sB[d];
    }
}

// ---------------- flash attention ----------------
__device__ __forceinline__ void cp16(float* dst, const float* src) {
    uint32_t d = (uint32_t)__cvta_generic_to_shared(dst);
    asm volatile("cp.async.cg.shared.global [%0], [%1], 16;\n" :: "r"(d), "l"(src));
}

// grid: (64 m-tiles, B), 256 threads, dynamic smem 99328B
__global__ __launch_bounds__(256, 2) void flash_kernel(float* __restrict__ out)
{
    extern __shared__ float sm[];
    float* sQ = sm;             // [32][64]      2048 floats
    float* sK = sm + 2048;      // [32][64]      2048 floats
    float* sP = sm + 4096;      // [64][PSTR]    4352 floats
    float* sV = sm + 8448;      // [64][256]    16384 floats

    int b      = blockIdx.y;
    int m_base = blockIdx.x * 64;
    int tid    = threadIdx.x;
    int tx = tid & 15, ty = tid >> 4;
    int m0 = ty * 4, n0 = tx * 4, cc0 = tx * 16;

    const float scale = 0.17677669529663689f;  // 1/sqrt(32)
    const float* Qb = g_Q + (size_t)b * DQK * N_PIX;
    for (int i = tid; i < 2048; i += 256) {
        int d = i >> 6, m = i & 63;
        sQ[i] = Qb[d * N_PIX + m_base + m] * scale;   // sQ[d][m], scale folded into Q
    }

    float rowM[4], rowL[4], O[4][16];
#pragma unroll
    for (int i = 0; i < 4; ++i) {
        rowM[i] = -1e30f; rowL[i] = 0.f;
#pragma unroll
        for (int k = 0; k < 16; ++k) O[i][k] = 0.f;
    }

    const float* Kb = g_K + (size_t)b * DQK * N_PIX;
    const float* Vb = g_V + (size_t)b * N_PIX * C_IN;
    __syncthreads();

    for (int t = 0; t < 64; ++t) {
        int n_base = t * 64;
        // K tile: [32][64] floats = 512 x 16B chunks
#pragma unroll
        for (int ch = 0; ch < 2; ++ch) {
            int id = tid + ch * 256;
            int d = id >> 4; int off = (id & 15) << 2;
            cp16(&sK[d * 64 + off], &Kb[d * N_PIX + n_base + off]);
        }
        // V tile: contiguous [64][256] = 4096 x 16B chunks
        const float* vsrc = Vb + (size_t)n_base * C_IN;
#pragma unroll
        for (int ch = 0; ch < 16; ++ch) {
            int id = (tid + ch * 256) << 2;
            cp16(&sV[id], &vsrc[id]);
        }
        asm volatile("cp.async.commit_group;\n" ::: "memory");
        asm volatile("cp.async.wait_group 0;\n" ::: "memory");
        __syncthreads();

        // ---- S = (scaled Q)^T K : thread computes 4m x 4n micro-tile ----
        float s[4][4];
#pragma unroll
        for (int i = 0; i < 4; ++i)
#pragma unroll
            for (int j = 0; j < 4; ++j) s[i][j] = 0.f;

#pragma unroll
        for (int d = 0; d < 32; ++d) {
            const float4 q4 = *(const float4*)&sQ[d * 64 + m0];
            const float4 k4 = *(const float4*)&sK[d * 64 + n0];
            float qa[4] = {q4.x, q4.y, q4.z, q4.w};
            float ka[4] = {k4.x, k4.y, k4.z, k4.w};
#pragma unroll
            for (int i = 0; i < 4; ++i)
#pragma unroll
                for (int j = 0; j < 4; ++j)
                    s[i][j] = fmaf(qa[i], ka[j], s[i][j]);
        }

        // ---- online softmax (rows live in registers, identical across the 16 tx lanes) ----
        float tmax[4], al[4], tsum[4], p[4][4];
#pragma unroll
        for (int i = 0; i < 4; ++i)
            tmax[i] = fmaxf(fmaxf(s[i][0], s[i][1]), fmaxf(s[i][2], s[i][3]));
#pragma unroll
        for (int o = 8; o >= 1; o >>= 1)
#pragma unroll
            for (int i = 0; i < 4; ++i)
                tmax[i] = fmaxf(tmax[i], __shfl_xor_sync(0xffffffffu, tmax[i], o));

#pragma unroll
        for (int i = 0; i < 4; ++i) {
            float nm = fmaxf(rowM[i], tmax[i]);
            al[i] = __expf(rowM[i] - nm);
            rowM[i] = nm;
            float ts = 0.f;
#pragma unroll
            for (int j = 0; j < 4; ++j) { p[i][j] = __expf(s[i][j] - nm); ts += p[i][j]; }
            tsum[i] = ts;
        }
#pragma unroll
        for (int o = 8; o >= 1; o >>= 1)
#pragma unroll
            for (int i = 0; i < 4; ++i)
                tsum[i] += __shfl_xor_sync(0xffffffffu, tsum[i], o);
#pragma unroll
        for (int i = 0; i < 4; ++i) {
            rowL[i] = rowL[i] * al[i] + tsum[i];
#pragma unroll
            for (int k = 0; k < 16; ++k) O[i][k] *= al[i];
        }
        // store P[n][m]
#pragma unroll
        for (int j = 0; j < 4; ++j) {
            float4 v; v.x = p[0][j]; v.y = p[1][j]; v.z = p[2][j]; v.w = p[3][j];
            *(float4*)&sP[(n0 + j) * PSTR + m0] = v;
        }
        __syncthreads();

        // ---- O += P V : thread owns 4m x 16c ----
#pragma unroll 2
        for (int n = 0; n < 64; ++n) {
            const float4 pv4 = *(const float4*)&sP[n * PSTR + m0];
            float pw[4] = {pv4.x, pv4.y, pv4.z, pv4.w};
            const float4* vr = (const float4*)&sV[n * 256 + cc0];
            float4 v0 = vr[0], v1 = vr[1], v2 = vr[2], v3 = vr[3];
            float vv[16] = {v0.x, v0.y, v0.z, v0.w, v1.x, v1.y, v1.z, v1.w,
                            v2.x, v2.y, v2.z, v2.w, v3.x, v3.y, v3.z, v3.w};
#pragma unroll
            for (int i = 0; i < 4; ++i)
#pragma unroll
                for (int k = 0; k < 16; ++k)
                    O[i][k] = fmaf(pw[i], vv[k], O[i][k]);
        }
        __syncthreads();
    }

    // ---- epilogue: out[b][c][m] ----
    float* ob = out + (size_t)b * C_IN * N_PIX + m_base + m0;
#pragma unroll
    for (int i = 0; i < 4; ++i) {
        float inv = 1.0f / rowL[i];
#pragma unroll
        for (int k = 0; k < 16; ++k)
            ob[(size_t)(cc0 + k) * N_PIX + i] = O[i][k] * inv;
    }
}

// ---------------- launch ----------------
extern "C" void kernel_launch(void* const* d_in, const int* in_sizes, int n_in,
                              void* d_out, int out_size)
{
    const float* x1 = (const float*)d_in[0];
    const float* x2 = (const float*)d_in[1];

    fold_kernel<<<320, 256>>>(
        (const float*)d_in[2],  (const float*)d_in[3],  (const float*)d_in[4],
        (const float*)d_in[5],  (const float*)d_in[6],  (const float*)d_in[7],
        (const float*)d_in[8],  (const float*)d_in[9],  (const float*)d_in[10],
        (const float*)d_in[11], (const float*)d_in[12], (const float*)d_in[13],
        (const float*)d_in[14], (const float*)d_in[15], (const float*)d_in[16],
        (const float*)d_in[17], (const float*)d_in[18], (const float*)d_in[19]);

    proj_kernel<<<dim3(N_PIX / 128, 10, B_SZ), 128>>>(x1, x2);

    const int smem_bytes = (2048 + 2048 + 64 * PSTR + 64 * 256) * 4;  // 99328
    cudaFuncSetAttribute(flash_kernel, cudaFuncAttributeMaxDynamicSharedMemorySize, smem_bytes);
    flash_kernel<<<dim3(64, B_SZ), 256, smem_bytes>>>((float*)d_out);
}

// round 2
// speedup vs baseline: 2.3229x; 2.3229x over previous
#include <cuda_runtime.h>
#include <cuda_bf16.h>
#include <cstdint>

#define N_PIX 4096
#define C_IN  256
#define DQK   32
#define B_SZ  4
#define SN    32            // n-tile (keys per iteration)
#define NT    (N_PIX / SN)  // 128 iterations
#define PSTR  68            // sP row stride in floats (64 m + 4 pad)

// ---------------- device scratch ----------------
__device__ __align__(16) float g_Q[B_SZ * DQK * N_PIX];     // [b][d][n]
__device__ __align__(16) float g_K[B_SZ * DQK * N_PIX];     // [b][d][n]
__device__ __align__(16) float g_V[B_SZ * N_PIX * C_IN];    // [b][n][c]
__device__ __align__(16) float g_Wf[320 * C_IN];            // folded weights
__device__ __align__(16) float g_Bf[320];                   // folded biases

// ---------------- f32x2 helpers (Blackwell FFMA2) ----------------
__device__ __forceinline__ unsigned long long pack2(float x, float y) {
    unsigned long long r;
    asm("mov.b64 %0, {%1, %2};" : "=l"(r) : "f"(x), "f"(y));
    return r;
}
__device__ __forceinline__ unsigned long long dup2(float x) { return pack2(x, x); }
__device__ __forceinline__ unsigned long long ffma2(unsigned long long a,
                                                    unsigned long long b,
                                                    unsigned long long c) {
    unsigned long long d;
    asm("fma.rn.f32x2 %0, %1, %2, %3;" : "=l"(d) : "l"(a), "l"(b), "l"(c));
    return d;
}
__device__ __forceinline__ unsigned long long mul2(unsigned long long a,
                                                   unsigned long long b) {
    unsigned long long d;
    asm("mul.rn.f32x2 %0, %1, %2;" : "=l"(d) : "l"(a), "l"(b));
    return d;
}
__device__ __forceinline__ void unpack2(unsigned long long v, float& x, float& y) {
    asm("mov.b64 {%0, %1}, %2;" : "=f"(x), "=f"(y) : "l"(v));
}

__device__ __forceinline__ void cp16(float* dst, const float* src) {
    uint32_t d = (uint32_t)__cvta_generic_to_shared(dst);
    asm volatile("cp.async.cg.shared.global [%0], [%1], 16;\n" :: "r"(d), "l"(src));
}

// ---------------- fold BN into 1x1-conv weights ----------------
__global__ void fold_kernel(
    const float* __restrict__ qw, const float* __restrict__ qb,
    const float* __restrict__ qg, const float* __restrict__ qbe,
    const float* __restrict__ qm, const float* __restrict__ qv,
    const float* __restrict__ kw, const float* __restrict__ kb,
    const float* __restrict__ kg, const float* __restrict__ kbe,
    const float* __restrict__ km, const float* __restrict__ kv,
    const float* __restrict__ vw, const float* __restrict__ vb,
    const float* __restrict__ vg, const float* __restrict__ vbe,
    const float* __restrict__ vm, const float* __restrict__ vv)
{
    int r = blockIdx.x;
    const float *w, *bb, *g, *be, *mn, *vr; int j;
    if (r < 32)      { w = qw; bb = qb; g = qg; be = qbe; mn = qm; vr = qv; j = r; }
    else if (r < 64) { w = kw; bb = kb; g = kg; be = kbe; mn = km; vr = kv; j = r - 32; }
    else             { w = vw; bb = vb; g = vg; be = vbe; mn = vm; vr = vv; j = r - 64; }
    float inv = g[j] * rsqrtf(vr[j] + 1e-5f);
    int c = threadIdx.x;
    g_Wf[r * C_IN + c] = w[j * C_IN + c] * inv;
    if (c == 0) g_Bf[r] = bb[j] * inv + be[j] - mn[j] * inv;
}

// ---------------- projection with FFMA2 ----------------
// grid: (N_PIX/128, 10 segs, B). seg 0 -> Q(x1), 1 -> K(x2), 2-9 -> V(x2)
__global__ __launch_bounds__(128) void proj_kernel(
    const float* __restrict__ x1, const float* __restrict__ x2)
{
    __shared__ float2 sW2[C_IN * 16];   // [c][dp] : pair (W[2dp][c], W[2dp+1][c])
    __shared__ float  sB[32];
    int seg = blockIdx.y, b = blockIdx.z;
    int tid = threadIdx.x;
    int n = blockIdx.x * 128 + tid;
    int r0 = seg * 32;
    for (int i = tid; i < C_IN * 16; i += 128) {
        int c = i >> 4, dp = i & 15;
        sW2[i] = make_float2(g_Wf[(r0 + 2 * dp) * C_IN + c],
                             g_Wf[(r0 + 2 * dp + 1) * C_IN + c]);
    }
    if (tid < 32) sB[tid] = g_Bf[r0 + tid];
    __syncthreads();

    const float* x  = (seg == 0) ? x1 : x2;
    const float* xb = x + (size_t)b * C_IN * N_PIX + n;

    unsigned long long acc2[16];
#pragma unroll
    for (int dp = 0; dp < 16; ++dp) acc2[dp] = 0ull;

#pragma unroll 2
    for (int c = 0; c < C_IN; c += 4) {
        float xv[4];
#pragma unroll
        for (int u = 0; u < 4; ++u) xv[u] = xb[(c + u) * N_PIX];
#pragma unroll
        for (int u = 0; u < 4; ++u) {
            unsigned long long xd = dup2(xv[u]);
            const ulonglong2* wr = (const ulonglong2*)&sW2[(c + u) * 16];
#pragma unroll
            for (int q = 0; q < 8; ++q) {
                ulonglong2 w = wr[q];
                acc2[2 * q]     = ffma2(w.x, xd, acc2[2 * q]);
                acc2[2 * q + 1] = ffma2(w.y, xd, acc2[2 * q + 1]);
            }
        }
    }

    float accs[32];
#pragma unroll
    for (int dp = 0; dp < 16; ++dp) unpack2(acc2[dp], accs[2 * dp], accs[2 * dp + 1]);

    if (seg < 2) {
        float* gg = (seg == 0) ? g_Q : g_K;
        float* gb = gg + (size_t)b * DQK * N_PIX + n;
#pragma unroll
        for (int d = 0; d < 32; ++d) gb[d * N_PIX] = accs[d] + sB[d];
    } else {
        int c0 = (seg - 2) * 32;
        float* gb = g_V + ((size_t)b * N_PIX + n) * C_IN + c0;
#pragma unroll
        for (int d = 0; d < 32; ++d) gb[d] = accs[d] + sB[d];
    }
}

// ---------------- flash attention, FFMA2 + conflict-free smem ----------------
// grid: (64 m-tiles, B), 256 threads.
// Phase-1 map (S+softmax): tx=tid&15 -> n0=2*tx ; ty=tid>>4 -> m0=4*ty (4m x 2n)
// Phase-2 map (PV):        l=tid&31 -> c chunks 4l, 4l+128 ; g=tid>>5 -> m0g=8g
__global__ __launch_bounds__(256, 2) void flash_kernel(float* __restrict__ out)
{
    extern __shared__ float smf[];
    float* sQ  = smf;              // [32 d][64 m]           2048
    float* sK  = smf + 2048;       // 2 x [32 d][32 n]       2048
    float* sV  = smf + 4096;       // 2 x [32 n][256 c]     16384
    float* sP  = smf + 20480;      // [32 n][PSTR]           2176
    float* sAl = smf + 22656;      // [64 m]                   64
    float* sL  = smf + 22720;      // [64 m]                   64

    int b      = blockIdx.y;
    int m_base = blockIdx.x * 64;
    int tid    = threadIdx.x;
    int tx = tid & 15, ty = tid >> 4;
    int m0 = ty * 4, n0 = tx * 2;
    int l = tid & 31, g = tid >> 5;
    int m0g = g * 8, c0 = l * 4, c1 = l * 4 + 128;

    const float scale = 0.17677669529663689f;  // 1/sqrt(32)
    const float* Qb = g_Q + (size_t)b * DQK * N_PIX;
    const float* Kb = g_K + (size_t)b * DQK * N_PIX;
    const float* Vb = g_V + (size_t)b * N_PIX * C_IN;

    for (int i = tid; i < 2048; i += 256) {
        int d = i >> 6, m = i & 63;
        sQ[i] = Qb[d * N_PIX + m_base + m] * scale;
    }

    float rowM[4], rowL[4];
    unsigned long long O2[4][8];   // [m-pair][c-slot], c-slot k<4 -> c0+k, else c1+k-4
#pragma unroll
    for (int i = 0; i < 4; ++i) {
        rowM[i] = -1e30f; rowL[i] = 0.f;
#pragma unroll
        for (int k = 0; k < 8; ++k) O2[i][k] = 0ull;
    }

    // prologue: load tile 0 into buf 0
    {
        int d = tid >> 3, off = (tid & 7) << 2;
        cp16(&sK[d * SN + off], &Kb[d * N_PIX + off]);
#pragma unroll
        for (int ch = 0; ch < 8; ++ch) {
            int id = tid + ch * 256;
            int n = id >> 6, co = (id & 63) << 2;
            cp16(&sV[n * 256 + co], &Vb[n * C_IN + co]);
        }
        asm volatile("cp.async.commit_group;\n" ::: "memory");
    }

    for (int t = 0; t < NT; ++t) {
        int buf = t & 1;
        const float* sKb = sK + buf * 1024;
        const float* sVb = sV + buf * 8192;

        if (t + 1 < NT) {
            int nb = (t + 1) * SN;
            float* sKn = sK + (buf ^ 1) * 1024;
            float* sVn = sV + (buf ^ 1) * 8192;
            int d = tid >> 3, off = (tid & 7) << 2;
            cp16(&sKn[d * SN + off], &Kb[d * N_PIX + nb + off]);
            const float* vs = Vb + (size_t)nb * C_IN;
#pragma unroll
            for (int ch = 0; ch < 8; ++ch) {
                int id = tid + ch * 256;
                int n = id >> 6, co = (id & 63) << 2;
                cp16(&sVn[n * 256 + co], &vs[n * C_IN + co]);
            }
            asm volatile("cp.async.commit_group;\n" ::: "memory");
            asm volatile("cp.async.wait_group 1;\n" ::: "memory");
        } else {
            asm volatile("cp.async.wait_group 0;\n" ::: "memory");
        }
        __syncthreads();

        // ---- S = Q^T K : s packed along m-pairs ----
        unsigned long long s2[2][2];    // [m-pair][j]
        s2[0][0] = s2[0][1] = s2[1][0] = s2[1][1] = 0ull;
#pragma unroll
        for (int d = 0; d < 32; ++d) {
            ulonglong2 qp = *(const ulonglong2*)&sQ[d * 64 + m0];   // (q_m0,q_m0+1),(q_m0+2,q_m0+3)
            float2 kk = *(const float2*)&sKb[d * SN + n0];
            unsigned long long k0 = dup2(kk.x), k1 = dup2(kk.y);
            s2[0][0] = ffma2(qp.x, k0, s2[0][0]);
            s2[1][0] = ffma2(qp.y, k0, s2[1][0]);
            s2[0][1] = ffma2(qp.x, k1, s2[0][1]);
            s2[1][1] = ffma2(qp.y, k1, s2[1][1]);
        }
        float s[4][2];
        unpack2(s2[0][0], s[0][0], s[1][0]);
        unpack2(s2[1][0], s[2][0], s[3][0]);
        unpack2(s2[0][1], s[0][1], s[1][1]);
        unpack2(s2[1][1], s[2][1], s[3][1]);

        // ---- online softmax over the 16 tx lanes (32 n) ----
        float tmax[4], al[4], p[4][2], tsum[4];
#pragma unroll
        for (int i = 0; i < 4; ++i) tmax[i] = fmaxf(s[i][0], s[i][1]);
#pragma unroll
        for (int o = 8; o >= 1; o >>= 1)
#pragma unroll
            for (int i = 0; i < 4; ++i)
                tmax[i] = fmaxf(tmax[i], __shfl_xor_sync(0xffffffffu, tmax[i], o));
#pragma unroll
        for (int i = 0; i < 4; ++i) {
            float nm = fmaxf(rowM[i], tmax[i]);
            al[i] = __expf(rowM[i] - nm);
            rowM[i] = nm;
            p[i][0] = __expf(s[i][0] - nm);
            p[i][1] = __expf(s[i][1] - nm);
            tsum[i] = p[i][0] + p[i][1];
        }
#pragma unroll
        for (int o = 8; o >= 1; o >>= 1)
#pragma unroll
            for (int i = 0; i < 4; ++i)
                tsum[i] += __shfl_xor_sync(0xffffffffu, tsum[i], o);
#pragma unroll
        for (int i = 0; i < 4; ++i) rowL[i] = rowL[i] * al[i] + tsum[i];

        // store P[n][m] (m contiguous) and alpha[m]
#pragma unroll
        for (int j = 0; j < 2; ++j) {
            float4 v; v.x = p[0][j]; v.y = p[1][j]; v.z = p[2][j]; v.w = p[3][j];
            *(float4*)&sP[(n0 + j) * PSTR + m0] = v;
        }
        if (tx == 0) {
#pragma unroll
            for (int i = 0; i < 4; ++i) sAl[m0 + i] = al[i];
        }
        __syncthreads();

        // ---- O += P V (phase-2 mapping) ----
#pragma unroll
        for (int mp = 0; mp < 4; ++mp) {
            unsigned long long a2 = *(const unsigned long long*)&sAl[m0g + 2 * mp];
#pragma unroll
            for (int k = 0; k < 8; ++k) O2[mp][k] = mul2(O2[mp][k], a2);
        }
#pragma unroll 2
        for (int n = 0; n < SN; ++n) {
            ulonglong2 p01 = *(const ulonglong2*)&sP[n * PSTR + m0g];      // pairs m0g..+3
            ulonglong2 p23 = *(const ulonglong2*)&sP[n * PSTR + m0g + 4];  // pairs m0g+4..+7
            float4 va  = *(const float4*)&sVb[n * 256 + c0];
            float4 vb4 = *(const float4*)&sVb[n * 256 + c1];
            unsigned long long vd[8] = {dup2(va.x),  dup2(va.y),  dup2(va.z),  dup2(va.w),
                                        dup2(vb4.x), dup2(vb4.y), dup2(vb4.z), dup2(vb4.w)};
#pragma unroll
            for (int k = 0; k < 8; ++k) {
                O2[0][k] = ffma2(p01.x, vd[k], O2[0][k]);
                O2[1][k] = ffma2(p01.y, vd[k], O2[1][k]);
                O2[2][k] = ffma2(p23.x, vd[k], O2[2][k]);
                O2[3][k] = ffma2(p23.y, vd[k], O2[3][k]);
            }
        }
        __syncthreads();
    }

    // ---- epilogue ----
    if (tx == 0) {
#pragma unroll
        for (int i = 0; i < 4; ++i) sL[m0 + i] = rowL[i];
    }
    __syncthreads();

    float* ob = out + (size_t)b * C_IN * N_PIX;
#pragma unroll
    for (int mp = 0; mp < 4; ++mp) {
        float2 Lp = *(const float2*)&sL[m0g + 2 * mp];
        unsigned long long inv2 = pack2(1.0f / Lp.x, 1.0f / Lp.y);
        int m = m_base + m0g + 2 * mp;
#pragma unroll
        for (int k = 0; k < 8; ++k) {
            int c = (k < 4) ? (c0 + k) : (c1 + k - 4);
            unsigned long long r = mul2(O2[mp][k], inv2);
            float lo, hi; unpack2(r, lo, hi);
            float2 st; st.x = lo; st.y = hi;
            *(float2*)&ob[(size_t)c * N_PIX + m] = st;   // consecutive m pair
        }
    }
}

// ---------------- launch ----------------
extern "C" void kernel_launch(void* const* d_in, const int* in_sizes, int n_in,
                              void* d_out, int out_size)
{
    const float* x1 = (const float*)d_in[0];
    const float* x2 = (const float*)d_in[1];

    fold_kernel<<<320, 256>>>(
        (const float*)d_in[2],  (const float*)d_in[3],  (const float*)d_in[4],
        (const float*)d_in[5],  (const float*)d_in[6],  (const float*)d_in[7],
        (const float*)d_in[8],  (const float*)d_in[9],  (const float*)d_in[10],
        (const float*)d_in[11], (const float*)d_in[12], (const float*)d_in[13],
        (const float*)d_in[14], (const float*)d_in[15], (const float*)d_in[16],
        (const float*)d_in[17], (const float*)d_in[18], (const float*)d_in[19]);

    proj_kernel<<<dim3(N_PIX / 128, 10, B_SZ), 128>>>(x1, x2);

    const int smem_bytes = (2048 + 2048 + 16384 + 2176 + 64 + 64) * 4;  // 91136
    cudaFuncSetAttribute(flash_kernel, cudaFuncAttributeMaxDynamicSharedMemorySize, smem_bytes);
    flash_kernel<<<dim3(64, B_SZ), 256, smem_bytes>>>((float*)d_out);
}

// round 8
// speedup vs baseline: 5.2272x; 2.2503x over previous
#include <cuda_runtime.h>
#include <cuda_bf16.h>
#include <cstdint>

#define N_PIX  4096
#define C_IN   256
#define B_SZ   4
#define TN     64
#define NTILES (N_PIX / TN)

// smem byte offsets (single stage)
#define SQHI 0                  // [64 m][32 d] bf16, row stride 80
#define SQLO 5120
#define SKHI 10240              // [64 n][32 d] bf16, stride 80
#define SKLO 15360
#define SPHI 20480              // [64 m][64 k] bf16, stride 144
#define SPLO 29696
#define SVHI 38912              // [64 k][256 c] bf16, stride 528
#define SVLO 72704
#define SLP  106496             // 2 x 64 float partial row sums
#define SMEM_TOTAL 107008

#define QK_STR 80
#define P_STR  144
#define V_STR  528

// ---------------- device scratch ----------------
__device__ __align__(16) __nv_bfloat16 g_Qs[B_SZ * N_PIX * 64];            // [b][m][hi32|lo32], scale*log2e folded
__device__ __align__(16) __nv_bfloat16 g_Ks[B_SZ * N_PIX * 64];            // [b][n][hi32|lo32]
__device__ __align__(16) __nv_bfloat16 g_Vh[(size_t)B_SZ * N_PIX * C_IN];  // [b][n][c] hi
__device__ __align__(16) __nv_bfloat16 g_Vl[(size_t)B_SZ * N_PIX * C_IN];  // [b][n][c] lo
__device__ __align__(16) float g_Wf[320 * C_IN];
__device__ float g_Bf[320];

// ---------------- helpers ----------------
__device__ __forceinline__ uint32_t s2u(const void* p) {
    uint32_t a;
    asm("{ .reg .u64 t; cvta.to.shared.u64 t, %1; cvt.u32.u64 %0, t; }" : "=r"(a) : "l"(p));
    return a;
}
__device__ __forceinline__ void cp16(uint32_t dst, const void* src) {
    asm volatile("cp.async.cg.shared.global [%0], [%1], 16;\n" :: "r"(dst), "l"(src));
}
#define CP_COMMIT() asm volatile("cp.async.commit_group;\n" ::: "memory")
#define CP_WAIT0()  asm volatile("cp.async.wait_group 0;\n" ::: "memory")

__device__ __forceinline__ void ldsm4(uint32_t& r0, uint32_t& r1, uint32_t& r2, uint32_t& r3, uint32_t a) {
    asm volatile("ldmatrix.sync.aligned.m8n8.x4.shared.b16 {%0,%1,%2,%3}, [%4];"
                 : "=r"(r0), "=r"(r1), "=r"(r2), "=r"(r3) : "r"(a));
}
__device__ __forceinline__ void ldsm4t(uint32_t& r0, uint32_t& r1, uint32_t& r2, uint32_t& r3, uint32_t a) {
    asm volatile("ldmatrix.sync.aligned.m8n8.x4.trans.shared.b16 {%0,%1,%2,%3}, [%4];"
                 : "=r"(r0), "=r"(r1), "=r"(r2), "=r"(r3) : "r"(a));
}
__device__ __forceinline__ void stsm4(uint32_t a, uint32_t r0, uint32_t r1, uint32_t r2, uint32_t r3) {
    asm volatile("stmatrix.sync.aligned.m8n8.x4.shared.b16 [%0], {%1,%2,%3,%4};"
                 :: "r"(a), "r"(r0), "r"(r1), "r"(r2), "r"(r3) : "memory");
}
__device__ __forceinline__ void mma_bf16(float* c, uint32_t a0, uint32_t a1, uint32_t a2, uint32_t a3,
                                         uint32_t b0, uint32_t b1) {
    asm volatile(
        "mma.sync.aligned.m16n8k16.row.col.f32.bf16.bf16.f32 "
        "{%0,%1,%2,%3}, {%4,%5,%6,%7}, {%8,%9}, {%0,%1,%2,%3};"
        : "+f"(c[0]), "+f"(c[1]), "+f"(c[2]), "+f"(c[3])
        : "r"(a0), "r"(a1), "r"(a2), "r"(a3), "r"(b0), "r"(b1));
}
__device__ __forceinline__ float ex2f(float x) {
    float e; asm("ex2.approx.ftz.f32 %0, %1;" : "=f"(e) : "f"(x)); return e;
}

__device__ __forceinline__ unsigned long long pack2(float x, float y) {
    unsigned long long r;
    asm("mov.b64 %0, {%1, %2};" : "=l"(r) : "f"(x), "f"(y));
    return r;
}
__device__ __forceinline__ unsigned long long dup2(float x) { return pack2(x, x); }
__device__ __forceinline__ unsigned long long ffma2(unsigned long long a, unsigned long long b,
                                                    unsigned long long c) {
    unsigned long long d;
    asm("fma.rn.f32x2 %0, %1, %2, %3;" : "=l"(d) : "l"(a), "l"(b), "l"(c));
    return d;
}
__device__ __forceinline__ void unpack2(unsigned long long v, float& x, float& y) {
    asm("mov.b64 {%0, %1}, %2;" : "=f"(x), "=f"(y) : "l"(v));
}

// ---------------- fold BN into 1x1-conv weights ----------------
__global__ void fold_kernel(
    const float* __restrict__ qw, const float* __restrict__ qb,
    const float* __restrict__ qg, const float* __restrict__ qbe,
    const float* __restrict__ qm, const float* __restrict__ qv,
    const float* __restrict__ kw, const float* __restrict__ kb,
    const float* __restrict__ kg, const float* __restrict__ kbe,
    const float* __restrict__ km, const float* __restrict__ kv,
    const float* __restrict__ vw, const float* __restrict__ vb,
    const float* __restrict__ vg, const float* __restrict__ vbe,
    const float* __restrict__ vm, const float* __restrict__ vv)
{
    int r = blockIdx.x;
    const float *w, *bb, *g, *be, *mn, *vr; int j;
    if (r < 32)      { w = qw; bb = qb; g = qg; be = qbe; mn = qm; vr = qv; j = r; }
    else if (r < 64) { w = kw; bb = kb; g = kg; be = kbe; mn = km; vr = kv; j = r - 32; }
    else             { w = vw; bb = vb; g = vg; be = vbe; mn = vm; vr = vv; j = r - 64; }
    float inv = g[j] * rsqrtf(vr[j] + 1e-5f);
    int c = threadIdx.x;
    g_Wf[r * C_IN + c] = w[j * C_IN + c] * inv;
    if (c == 0) g_Bf[r] = bb[j] * inv + be[j] - mn[j] * inv;
}

// ---------------- projection -> bf16 hi/lo operands ----------------
// grid: (N_PIX/128, 10 segs, B). seg 0 -> Q(x1), 1 -> K(x2), 2-9 -> V(x2)
__global__ __launch_bounds__(128) void proj_kernel(
    const float* __restrict__ x1, const float* __restrict__ x2)
{
    __shared__ float2 sW2[C_IN * 16];
    int seg = blockIdx.y, b = blockIdx.z;
    int tid = threadIdx.x;
    int n = blockIdx.x * 128 + tid;
    int r0 = seg * 32;
    for (int i = tid; i < C_IN * 16; i += 128) {
        int c = i >> 4, dp = i & 15;
        sW2[i] = make_float2(g_Wf[(r0 + 2 * dp) * C_IN + c],
                             g_Wf[(r0 + 2 * dp + 1) * C_IN + c]);
    }
    __syncthreads();

    const float* x  = (seg == 0) ? x1 : x2;
    const float* xb = x + (size_t)b * C_IN * N_PIX + n;

    unsigned long long acc2[16];
#pragma unroll
    for (int dp = 0; dp < 16; ++dp) acc2[dp] = 0ull;

#pragma unroll 2
    for (int c = 0; c < C_IN; c += 4) {
        float xv[4];
#pragma unroll
        for (int u = 0; u < 4; ++u) xv[u] = xb[(c + u) * N_PIX];
#pragma unroll
        for (int u = 0; u < 4; ++u) {
            unsigned long long xd = dup2(xv[u]);
            const ulonglong2* wr = (const ulonglong2*)&sW2[(c + u) * 16];
#pragma unroll
            for (int q = 0; q < 8; ++q) {
                ulonglong2 w = wr[q];
                acc2[2 * q]     = ffma2(w.x, xd, acc2[2 * q]);
                acc2[2 * q + 1] = ffma2(w.y, xd, acc2[2 * q + 1]);
            }
        }
    }

    float f[32];
#pragma unroll
    for (int dp = 0; dp < 16; ++dp) unpack2(acc2[dp], f[2 * dp], f[2 * dp + 1]);
#pragma unroll
    for (int d = 0; d < 32; ++d) f[d] += g_Bf[r0 + d];

    if (seg == 0) {
        const float qs = 0.17677669529663689f * 1.4426950408889634f;  // scale * log2(e)
#pragma unroll
        for (int d = 0; d < 32; ++d) f[d] *= qs;
    }

    // hi/lo split
    uint32_t uh[16], ul[16];
#pragma unroll
    for (int j = 0; j < 16; ++j) {
        float a = f[2 * j], c = f[2 * j + 1];
        __nv_bfloat162 hi2 = __floats2bfloat162_rn(a, c);
        float ra = a - __low2float(hi2);
        float rc = c - __high2float(hi2);
        __nv_bfloat162 lo2 = __floats2bfloat162_rn(ra, rc);
        uh[j] = *reinterpret_cast<uint32_t*>(&hi2);
        ul[j] = *reinterpret_cast<uint32_t*>(&lo2);
    }

    if (seg < 2) {
        // row: [hi 32 bf16 | lo 32 bf16] = 128B
        char* dst = (char*)((seg == 0) ? g_Qs : g_Ks) + ((size_t)(b * N_PIX + n)) * 128;
#pragma unroll
        for (int q = 0; q < 4; ++q) {
            *(uint4*)(dst + q * 16)      = make_uint4(uh[4 * q], uh[4 * q + 1], uh[4 * q + 2], uh[4 * q + 3]);
            *(uint4*)(dst + 64 + q * 16) = make_uint4(ul[4 * q], ul[4 * q + 1], ul[4 * q + 2], ul[4 * q + 3]);
        }
    } else {
        int c0 = (seg - 2) * 32;
        char* dh = (char*)g_Vh + (((size_t)(b * N_PIX + n)) * C_IN + c0) * 2;
        char* dl = (char*)g_Vl + (((size_t)(b * N_PIX + n)) * C_IN + c0) * 2;
#pragma unroll
        for (int q = 0; q < 4; ++q) {
            *(uint4*)(dh + q * 16) = make_uint4(uh[4 * q], uh[4 * q + 1], uh[4 * q + 2], uh[4 * q + 3]);
            *(uint4*)(dl + q * 16) = make_uint4(ul[4 * q], ul[4 * q + 1], ul[4 * q + 2], ul[4 * q + 3]);
        }
    }
}

// ---------------- flash attention via mma.sync (bf16 hi/lo, 3-term) ----------------
// grid: (N_PIX/64, B), 256 threads = 8 warps.
// S phase:  warp w -> m-slice (w&3)*16, n-half (w>>2)*32
// PV phase: warp w -> m-slice (w&3)*16, c-half (w>>2)*128
__global__ __launch_bounds__(256, 2) void flash_mma(float* __restrict__ out)
{
    extern __shared__ __align__(16) char sm[];
    const uint32_t sb = s2u(sm);
    const int tid  = threadIdx.x;
    const int warp = tid >> 5;
    const int lane = tid & 31;
    const int ms   = (warp & 3) * 16;
    const int half = warp >> 2;
    const int b    = blockIdx.y;
    const int m_base = blockIdx.x * 64;

    // ---- Q tiles (persistent) ----
    {
        const char* gq = (const char*)g_Qs + ((size_t)(b * N_PIX + m_base)) * 128;
        for (int i = tid; i < 512; i += 256) {
            int m = i >> 3, q = i & 7;
            uint4 v = *(const uint4*)(gq + (size_t)m * 128 + q * 16);
            if (q < 4) *(uint4*)(sm + SQHI + m * QK_STR + q * 16) = v;
            else       *(uint4*)(sm + SQLO + m * QK_STR + (q - 4) * 16) = v;
        }
    }

    float O[16][4];
#pragma unroll
    for (int j = 0; j < 16; ++j)
#pragma unroll
        for (int k = 0; k < 4; ++k) O[j][k] = 0.f;
    float rs0 = 0.f, rs1 = 0.f;

    const char* gkb = (const char*)g_Ks + ((size_t)b * N_PIX) * 128;
    const char* ghb = (const char*)g_Vh + ((size_t)b * N_PIX) * C_IN * 2;
    const char* glb = (const char*)g_Vl + ((size_t)b * N_PIX) * C_IN * 2;

#pragma unroll 1
    for (int t = 0; t < NTILES; ++t) {
        // ---- load K + V tiles via cp.async ----
        {
            const char* gk = gkb + (size_t)t * TN * 128;
            for (int i = tid; i < 512; i += 256) {
                int n = i >> 3, q = i & 7;
                uint32_t d = (q < 4) ? (sb + SKHI + n * QK_STR + q * 16)
                                     : (sb + SKLO + n * QK_STR + (q - 4) * 16);
                cp16(d, gk + (size_t)n * 128 + q * 16);
            }
            const char* gh = ghb + (size_t)t * TN * C_IN * 2;
            const char* gl = glb + (size_t)t * TN * C_IN * 2;
            for (int i = tid; i < 2048; i += 256) {
                int n = i >> 5, q = i & 31;
                cp16(sb + SVHI + n * V_STR + q * 16, gh + (size_t)n * 512 + q * 16);
                cp16(sb + SVLO + n * V_STR + q * 16, gl + (size_t)n * 512 + q * 16);
            }
        }
        CP_COMMIT();
        CP_WAIT0();
        __syncthreads();

        // ---- S = Q K^T (3-term), warp tile m16 x n32 ----
        float acc[4][4];
#pragma unroll
        for (int j = 0; j < 4; ++j)
#pragma unroll
            for (int k = 0; k < 4; ++k) acc[j][k] = 0.f;

#pragma unroll
        for (int kt = 0; kt < 2; ++kt) {
            uint32_t ah0, ah1, ah2, ah3, al0, al1, al2, al3;
            {
                uint32_t a = sb + SQHI + (ms + (lane & 15)) * QK_STR + kt * 32 + (lane >> 4) * 16;
                ldsm4(ah0, ah1, ah2, ah3, a);
                a = sb + SQLO + (ms + (lane & 15)) * QK_STR + kt * 32 + (lane >> 4) * 16;
                ldsm4(al0, al1, al2, al3, a);
            }
#pragma unroll
            for (int nb = 0; nb < 2; ++nb) {
                int nbase = half * 32 + nb * 16;
                uint32_t row = nbase + ((lane >> 4) << 3) + (lane & 7);
                uint32_t col = kt * 32 + ((lane >> 3) & 1) * 16;
                uint32_t bh0, bh1, bh2, bh3, bl0, bl1, bl2, bl3;
                ldsm4(bh0, bh1, bh2, bh3, sb + SKHI + row * QK_STR + col);
                ldsm4(bl0, bl1, bl2, bl3, sb + SKLO + row * QK_STR + col);
                mma_bf16(acc[2 * nb],     ah0, ah1, ah2, ah3, bh0, bh1);
                mma_bf16(acc[2 * nb],     ah0, ah1, ah2, ah3, bl0, bl1);
                mma_bf16(acc[2 * nb],     al0, al1, al2, al3, bh0, bh1);
                mma_bf16(acc[2 * nb + 1], ah0, ah1, ah2, ah3, bh2, bh3);
                mma_bf16(acc[2 * nb + 1], ah0, ah1, ah2, ah3, bl2, bl3);
                mma_bf16(acc[2 * nb + 1], al0, al1, al2, al3, bh2, bh3);
            }
        }

        // ---- P = exp2(S) unnormalized; accumulate row sums; pack hi/lo ----
        uint32_t p01h[4], p23h[4], p01l[4], p23l[4];
#pragma unroll
        for (int j = 0; j < 4; ++j) {
            float p0 = ex2f(acc[j][0]), p1 = ex2f(acc[j][1]);
            float p2 = ex2f(acc[j][2]), p3 = ex2f(acc[j][3]);
            rs0 += p0 + p1;
            rs1 += p2 + p3;
            __nv_bfloat162 h01 = __floats2bfloat162_rn(p0, p1);
            __nv_bfloat162 h23 = __floats2bfloat162_rn(p2, p3);
            __nv_bfloat162 l01 = __floats2bfloat162_rn(p0 - __low2float(h01), p1 - __high2float(h01));
            __nv_bfloat162 l23 = __floats2bfloat162_rn(p2 - __low2float(h23), p3 - __high2float(h23));
            p01h[j] = *reinterpret_cast<uint32_t*>(&h01);
            p23h[j] = *reinterpret_cast<uint32_t*>(&h23);
            p01l[j] = *reinterpret_cast<uint32_t*>(&l01);
            p23l[j] = *reinterpret_cast<uint32_t*>(&l23);
        }

        // ---- stmatrix P tiles: [64 m][64 k], warp writes m16 x k32 at col half*32 ----
        {
            int g = lane >> 3;
            uint32_t row = ms + (g & 1) * 8 + (lane & 7);
            uint32_t colb = half * 64 + (g >> 1) * 16;   // j-pair base: 2 tiles x 16B
            uint32_t a0 = sb + SPHI + row * P_STR + colb;
            uint32_t a1 = a0 + 32;                        // j-pair 1
            stsm4(a0, p01h[0], p23h[0], p01h[1], p23h[1]);
            stsm4(a1, p01h[2], p23h[2], p01h[3], p23h[3]);
            a0 = sb + SPLO + row * P_STR + colb;
            a1 = a0 + 32;
            stsm4(a0, p01l[0], p23l[0], p01l[1], p23l[1]);
            stsm4(a1, p01l[2], p23l[2], p01l[3], p23l[3]);
        }
        __syncthreads();

        // ---- O += P V (3-term), warp tile m16 x c128 ----
#pragma unroll
        for (int kt = 0; kt < 4; ++kt) {
            uint32_t ah0, ah1, ah2, ah3, al0, al1, al2, al3;
            {
                uint32_t a = sb + SPHI + (ms + (lane & 15)) * P_STR + kt * 32 + (lane >> 4) * 16;
                ldsm4(ah0, ah1, ah2, ah3, a);
                a = sb + SPLO + (ms + (lane & 15)) * P_STR + kt * 32 + (lane >> 4) * 16;
                ldsm4(al0, al1, al2, al3, a);
            }
            uint32_t vrow = kt * 16 + ((lane >> 3) & 1) * 8 + (lane & 7);
#pragma unroll
            for (int blk = 0; blk < 8; ++blk) {
                uint32_t colb = half * 256 + blk * 32 + ((lane >> 4) & 1) * 16;
                uint32_t bh0, bh1, bh2, bh3, bl0, bl1, bl2, bl3;
                ldsm4t(bh0, bh1, bh2, bh3, sb + SVHI + vrow * V_STR + colb);
                ldsm4t(bl0, bl1, bl2, bl3, sb + SVLO + vrow * V_STR + colb);
                int j = blk * 2;
                mma_bf16(O[j],     ah0, ah1, ah2, ah3, bh0, bh1);
                mma_bf16(O[j],     ah0, ah1, ah2, ah3, bl0, bl1);
                mma_bf16(O[j],     al0, al1, al2, al3, bh0, bh1);
                mma_bf16(O[j + 1], ah0, ah1, ah2, ah3, bh2, bh3);
                mma_bf16(O[j + 1], ah0, ah1, ah2, ah3, bl2, bl3);
                mma_bf16(O[j + 1], al0, al1, al2, al3, bh2, bh3);
            }
        }
        __syncthreads();
    }

    // ---- epilogue: combine row sums, normalize, store ----
    rs0 += __shfl_xor_sync(0xffffffffu, rs0, 1);
    rs0 += __shfl_xor_sync(0xffffffffu, rs0, 2);
    rs1 += __shfl_xor_sync(0xffffffffu, rs1, 1);
    rs1 += __shfl_xor_sync(0xffffffffu, rs1, 2);
    float* sLp = (float*)(sm + SLP);
    if ((lane & 3) == 0) {
        sLp[half * 64 + ms + (lane >> 2)]     = rs0;
        sLp[half * 64 + ms + (lane >> 2) + 8] = rs1;
    }
    __syncthreads();

    int r0 = ms + (lane >> 2);
    float inv0 = 1.0f / (sLp[r0] + sLp[64 + r0]);
    float inv1 = 1.0f / (sLp[r0 + 8] + sLp[64 + r0 + 8]);

    float* ob = out + (size_t)b * C_IN * N_PIX + m_base;
#pragma unroll
    for (int j = 0; j < 16; ++j) {
        int c = half * 128 + j * 8 + 2 * (lane & 3);
        ob[(size_t)c * N_PIX + r0]           = O[j][0] * inv0;
        ob[(size_t)(c + 1) * N_PIX + r0]     = O[j][1] * inv0;
        ob[(size_t)c * N_PIX + r0 + 8]       = O[j][2] * inv1;
        ob[(size_t)(c + 1) * N_PIX + r0 + 8] = O[j][3] * inv1;
    }
}

// ---------------- launch ----------------
extern "C" void kernel_launch(void* const* d_in, const int* in_sizes, int n_in,
                              void* d_out, int out_size)
{
    const float* x1 = (const float*)d_in[0];
    const float* x2 = (const float*)d_in[1];

    fold_kernel<<<320, 256>>>(
        (const float*)d_in[2],  (const float*)d_in[3],  (const float*)d_in[4],
        (const float*)d_in[5],  (const float*)d_in[6],  (const float*)d_in[7],
        (const float*)d_in[8],  (const float*)d_in[9],  (const float*)d_in[10],
        (const float*)d_in[11], (const float*)d_in[12], (const float*)d_in[13],
        (const float*)d_in[14], (const float*)d_in[15], (const float*)d_in[16],
        (const float*)d_in[17], (const float*)d_in[18], (const float*)d_in[19]);

    proj_kernel<<<dim3(N_PIX / 128, 10, B_SZ), 128>>>(x1, x2);

    cudaFuncSetAttribute(flash_mma, cudaFuncAttributeMaxDynamicSharedMemorySize, SMEM_TOTAL);
    flash_mma<<<dim3(N_PIX / 64, B_SZ), 256, SMEM_TOTAL>>>((float*)d_out);
}

// round 9
// speedup vs baseline: 7.1528x; 1.3684x over previous
#include <cuda_runtime.h>
#include <cuda_fp16.h>
#include <cstdint>

#define N_PIX  4096
#define C_IN   256
#define B_SZ   4
#define TN     64
#define NTILES (N_PIX / TN)
#define M_TILE 128

// smem byte offsets
#define SQHI 0                       // [128 m][32 d] fp16, stride 80
#define SQLO 10240
#define SKBASE(st) (20480 + (st) * 10240)   // hi at +0, lo at +5120; [64 n][32 d]
#define SVBASE(st) (40960 + (st) * 33792)   // [64 n][256 c] fp16 single, stride 528
#define SPHI 108544                  // [128 m][64 k] fp16, stride 144
#define SPLO 126976
#define SLP  145408                  // 2 x 128 float partial row sums
#define SMEM_TOTAL 146432

#define QK_STR 80
#define P_STR  144
#define V_STR  528

// ---------------- device scratch ----------------
__device__ __align__(16) __half g_Qs[B_SZ * N_PIX * 64];            // [b][m][hi32|lo32], scale*log2e folded
__device__ __align__(16) __half g_Ks[B_SZ * N_PIX * 64];            // [b][n][hi32|lo32]
__device__ __align__(16) __half g_V[(size_t)B_SZ * N_PIX * C_IN];   // [b][n][c] single fp16
__device__ __align__(16) float g_Wf[320 * C_IN];
__device__ float g_Bf[320];

// ---------------- helpers ----------------
__device__ __forceinline__ uint32_t s2u(const void* p) {
    uint32_t a;
    asm("{ .reg .u64 t; cvta.to.shared.u64 t, %1; cvt.u32.u64 %0, t; }" : "=r"(a) : "l"(p));
    return a;
}
__device__ __forceinline__ void cp16(uint32_t dst, const void* src) {
    asm volatile("cp.async.cg.shared.global [%0], [%1], 16;\n" :: "r"(dst), "l"(src));
}
#define CP_COMMIT() asm volatile("cp.async.commit_group;\n" ::: "memory")
#define CP_WAIT0()  asm volatile("cp.async.wait_group 0;\n" ::: "memory")
#define CP_WAIT1()  asm volatile("cp.async.wait_group 1;\n" ::: "memory")

__device__ __forceinline__ void ldsm4(uint32_t& r0, uint32_t& r1, uint32_t& r2, uint32_t& r3, uint32_t a) {
    asm volatile("ldmatrix.sync.aligned.m8n8.x4.shared.b16 {%0,%1,%2,%3}, [%4];"
                 : "=r"(r0), "=r"(r1), "=r"(r2), "=r"(r3) : "r"(a));
}
__device__ __forceinline__ void ldsm4t(uint32_t& r0, uint32_t& r1, uint32_t& r2, uint32_t& r3, uint32_t a) {
    asm volatile("ldmatrix.sync.aligned.m8n8.x4.trans.shared.b16 {%0,%1,%2,%3}, [%4];"
                 : "=r"(r0), "=r"(r1), "=r"(r2), "=r"(r3) : "r"(a));
}
__device__ __forceinline__ void stsm4(uint32_t a, uint32_t r0, uint32_t r1, uint32_t r2, uint32_t r3) {
    asm volatile("stmatrix.sync.aligned.m8n8.x4.shared.b16 [%0], {%1,%2,%3,%4};"
                 :: "r"(a), "r"(r0), "r"(r1), "r"(r2), "r"(r3) : "memory");
}
__device__ __forceinline__ void mma_f16(float* c, uint32_t a0, uint32_t a1, uint32_t a2, uint32_t a3,
                                        uint32_t b0, uint32_t b1) {
    asm volatile(
        "mma.sync.aligned.m16n8k16.row.col.f32.f16.f16.f32 "
        "{%0,%1,%2,%3}, {%4,%5,%6,%7}, {%8,%9}, {%0,%1,%2,%3};"
        : "+f"(c[0]), "+f"(c[1]), "+f"(c[2]), "+f"(c[3])
        : "r"(a0), "r"(a1), "r"(a2), "r"(a3), "r"(b0), "r"(b1));
}
__device__ __forceinline__ float ex2f(float x) {
    float e; asm("ex2.approx.ftz.f32 %0, %1;" : "=f"(e) : "f"(x)); return e;
}

__device__ __forceinline__ unsigned long long pack2(float x, float y) {
    unsigned long long r;
    asm("mov.b64 %0, {%1, %2};" : "=l"(r) : "f"(x), "f"(y));
    return r;
}
__device__ __forceinline__ unsigned long long dup2(float x) { return pack2(x, x); }
__device__ __forceinline__ unsigned long long ffma2(unsigned long long a, unsigned long long b,
                                                    unsigned long long c) {
    unsigned long long d;
    asm("fma.rn.f32x2 %0, %1, %2, %3;" : "=l"(d) : "l"(a), "l"(b), "l"(c));
    return d;
}
__device__ __forceinline__ void unpack2(unsigned long long v, float& x, float& y) {
    asm("mov.b64 {%0, %1}, %2;" : "=f"(x), "=f"(y) : "l"(v));
}

// ---------------- fold BN into 1x1-conv weights ----------------
__global__ void fold_kernel(
    const float* __restrict__ qw, const float* __restrict__ qb,
    const float* __restrict__ qg, const float* __restrict__ qbe,
    const float* __restrict__ qm, const float* __restrict__ qv,
    const float* __restrict__ kw, const float* __restrict__ kb,
    const float* __restrict__ kg, const float* __restrict__ kbe,
    const float* __restrict__ km, const float* __restrict__ kv,
    const float* __restrict__ vw, const float* __restrict__ vb,
    const float* __restrict__ vg, const float* __restrict__ vbe,
    const float* __restrict__ vm, const float* __restrict__ vv)
{
    int r = blockIdx.x;
    const float *w, *bb, *g, *be, *mn, *vr; int j;
    if (r < 32)      { w = qw; bb = qb; g = qg; be = qbe; mn = qm; vr = qv; j = r; }
    else if (r < 64) { w = kw; bb = kb; g = kg; be = kbe; mn = km; vr = kv; j = r - 32; }
    else             { w = vw; bb = vb; g = vg; be = vbe; mn = vm; vr = vv; j = r - 64; }
    float inv = g[j] * rsqrtf(vr[j] + 1e-5f);
    int c = threadIdx.x;
    g_Wf[r * C_IN + c] = w[j * C_IN + c] * inv;
    if (c == 0) g_Bf[r] = bb[j] * inv + be[j] - mn[j] * inv;
}

// ---------------- projection -> fp16 operands ----------------
// grid: (N_PIX/128, 10 segs, B). seg 0 -> Q(x1), 1 -> K(x2), 2-9 -> V(x2)
__global__ __launch_bounds__(128) void proj_kernel(
    const float* __restrict__ x1, const float* __restrict__ x2)
{
    __shared__ float2 sW2[C_IN * 16];
    int seg = blockIdx.y, b = blockIdx.z;
    int tid = threadIdx.x;
    int n = blockIdx.x * 128 + tid;
    int r0 = seg * 32;
    for (int i = tid; i < C_IN * 16; i += 128) {
        int c = i >> 4, dp = i & 15;
        sW2[i] = make_float2(g_Wf[(r0 + 2 * dp) * C_IN + c],
                             g_Wf[(r0 + 2 * dp + 1) * C_IN + c]);
    }
    __syncthreads();

    const float* x  = (seg == 0) ? x1 : x2;
    const float* xb = x + (size_t)b * C_IN * N_PIX + n;

    unsigned long long acc2[16];
#pragma unroll
    for (int dp = 0; dp < 16; ++dp) acc2[dp] = 0ull;

#pragma unroll 2
    for (int c = 0; c < C_IN; c += 4) {
        float xv[4];
#pragma unroll
        for (int u = 0; u < 4; ++u) xv[u] = xb[(c + u) * N_PIX];
#pragma unroll
        for (int u = 0; u < 4; ++u) {
            unsigned long long xd = dup2(xv[u]);
            const ulonglong2* wr = (const ulonglong2*)&sW2[(c + u) * 16];
#pragma unroll
            for (int q = 0; q < 8; ++q) {
                ulonglong2 w = wr[q];
                acc2[2 * q]     = ffma2(w.x, xd, acc2[2 * q]);
                acc2[2 * q + 1] = ffma2(w.y, xd, acc2[2 * q + 1]);
            }
        }
    }

    float f[32];
#pragma unroll
    for (int dp = 0; dp < 16; ++dp) unpack2(acc2[dp], f[2 * dp], f[2 * dp + 1]);
#pragma unroll
    for (int d = 0; d < 32; ++d) f[d] += g_Bf[r0 + d];

    if (seg == 0) {
        const float qs = 0.17677669529663689f * 1.4426950408889634f;  // scale * log2(e)
#pragma unroll
        for (int d = 0; d < 32; ++d) f[d] *= qs;
    }

    if (seg < 2) {
        // hi/lo fp16 split; row: [hi 32 fp16 | lo 32 fp16] = 128B
        uint32_t uh[16], ul[16];
#pragma unroll
        for (int j = 0; j < 16; ++j) {
            float a = f[2 * j], c = f[2 * j + 1];
            __half2 h2 = __floats2half2_rn(a, c);
            float ra = a - __low2float(h2);
            float rc = c - __high2float(h2);
            __half2 l2 = __floats2half2_rn(ra, rc);
            uh[j] = *reinterpret_cast<uint32_t*>(&h2);
            ul[j] = *reinterpret_cast<uint32_t*>(&l2);
        }
        char* dst = (char*)((seg == 0) ? g_Qs : g_Ks) + ((size_t)(b * N_PIX + n)) * 128;
#pragma unroll
        for (int q = 0; q < 4; ++q) {
            *(uint4*)(dst + q * 16)      = make_uint4(uh[4 * q], uh[4 * q + 1], uh[4 * q + 2], uh[4 * q + 3]);
            *(uint4*)(dst + 64 + q * 16) = make_uint4(ul[4 * q], ul[4 * q + 1], ul[4 * q + 2], ul[4 * q + 3]);
        }
    } else {
        // V: single fp16
        int c0 = (seg - 2) * 32;
        uint32_t uh[16];
#pragma unroll
        for (int j = 0; j < 16; ++j) {
            __half2 h2 = __floats2half2_rn(f[2 * j], f[2 * j + 1]);
            uh[j] = *reinterpret_cast<uint32_t*>(&h2);
        }
        char* dh = (char*)g_V + (((size_t)(b * N_PIX + n)) * C_IN + c0) * 2;
#pragma unroll
        for (int q = 0; q < 4; ++q)
            *(uint4*)(dh + q * 16) = make_uint4(uh[4 * q], uh[4 * q + 1], uh[4 * q + 2], uh[4 * q + 3]);
    }
}

// ---------------- flash attention: fp16 mma.sync, 2-stage pipeline ----------------
// grid: (N_PIX/128, B), 512 threads = 16 warps, occ 1.
// S phase:  warp w -> m-slice (w&7)*16, n-half (w>>3)*32
// PV phase: warp w -> m-slice (w&7)*16, c-half (w>>3)*128
__global__ __launch_bounds__(512, 1) void flash_mma(float* __restrict__ out)
{
    extern __shared__ __align__(16) char sm[];
    const uint32_t sb = s2u(sm);
    const int tid  = threadIdx.x;
    const int warp = tid >> 5;
    const int lane = tid & 31;
    const int ms   = (warp & 7) * 16;
    const int half = warp >> 3;
    const int b    = blockIdx.y;
    const int m_base = blockIdx.x * M_TILE;

    const char* gkb = (const char*)g_Ks + ((size_t)b * N_PIX) * 128;
    const char* gvb = (const char*)g_V + ((size_t)b * N_PIX) * C_IN * 2;

    // ---- Q tiles (persistent) ----
    {
        const char* gq = (const char*)g_Qs + ((size_t)(b * N_PIX + m_base)) * 128;
        for (int i = tid; i < 1024; i += 512) {
            int m = i >> 3, q = i & 7;
            uint4 v = *(const uint4*)(gq + (size_t)m * 128 + q * 16);
            if (q < 4) *(uint4*)(sm + SQHI + m * QK_STR + q * 16) = v;
            else       *(uint4*)(sm + SQLO + m * QK_STR + (q - 4) * 16) = v;
        }
    }

    float O[16][4];
#pragma unroll
    for (int j = 0; j < 16; ++j)
#pragma unroll
        for (int k = 0; k < 4; ++k) O[j][k] = 0.f;
    float rs0 = 0.f, rs1 = 0.f;

    // ---- tile loader (cp.async) ----
    auto load_kv = [&](int t, int st) {
        const char* gk = gkb + (size_t)t * TN * 128;
        {
            int n = tid >> 3, q = tid & 7;
            uint32_t d = (q < 4) ? (sb + SKBASE(st) + n * QK_STR + q * 16)
                                 : (sb + SKBASE(st) + 5120 + n * QK_STR + (q - 4) * 16);
            cp16(d, gk + (size_t)n * 128 + q * 16);
        }
        const char* gv = gvb + (size_t)t * TN * C_IN * 2;
        for (int i = tid; i < 2048; i += 512) {
            int n = i >> 5, q = i & 31;
            cp16(sb + SVBASE(st) + n * V_STR + q * 16, gv + (size_t)n * 512 + q * 16);
        }
    };

    load_kv(0, 0);
    CP_COMMIT();

#pragma unroll 1
    for (int t = 0; t < NTILES; ++t) {
        const int st = t & 1;
        if (t + 1 < NTILES) {
            load_kv(t + 1, st ^ 1);
            CP_COMMIT();
            CP_WAIT1();
        } else {
            CP_WAIT0();
        }
        __syncthreads();

        // ---- S = Q K^T (3-term fp16 hi/lo), warp tile m16 x n32 ----
        float acc[4][4];
#pragma unroll
        for (int j = 0; j < 4; ++j)
#pragma unroll
            for (int k = 0; k < 4; ++k) acc[j][k] = 0.f;

#pragma unroll
        for (int kt = 0; kt < 2; ++kt) {
            uint32_t ah0, ah1, ah2, ah3, al0, al1, al2, al3;
            {
                uint32_t a = sb + SQHI + (ms + (lane & 15)) * QK_STR + kt * 32 + (lane >> 4) * 16;
                ldsm4(ah0, ah1, ah2, ah3, a);
                a = sb + SQLO + (ms + (lane & 15)) * QK_STR + kt * 32 + (lane >> 4) * 16;
                ldsm4(al0, al1, al2, al3, a);
            }
#pragma unroll
            for (int nb = 0; nb < 2; ++nb) {
                int nbase = half * 32 + nb * 16;
                uint32_t row = nbase + ((lane >> 4) << 3) + (lane & 7);
                uint32_t col = kt * 32 + ((lane >> 3) & 1) * 16;
                uint32_t bh0, bh1, bh2, bh3, bl0, bl1, bl2, bl3;
                ldsm4(bh0, bh1, bh2, bh3, sb + SKBASE(st) + row * QK_STR + col);
                ldsm4(bl0, bl1, bl2, bl3, sb + SKBASE(st) + 5120 + row * QK_STR + col);
                mma_f16(acc[2 * nb],     ah0, ah1, ah2, ah3, bh0, bh1);
                mma_f16(acc[2 * nb],     ah0, ah1, ah2, ah3, bl0, bl1);
                mma_f16(acc[2 * nb],     al0, al1, al2, al3, bh0, bh1);
                mma_f16(acc[2 * nb + 1], ah0, ah1, ah2, ah3, bh2, bh3);
                mma_f16(acc[2 * nb + 1], ah0, ah1, ah2, ah3, bl2, bl3);
                mma_f16(acc[2 * nb + 1], al0, al1, al2, al3, bh2, bh3);
            }
        }

        // ---- P = exp2(S) unnormalized; row sums; pack fp16 hi/lo ----
        uint32_t p01h[4], p23h[4], p01l[4], p23l[4];
#pragma unroll
        for (int j = 0; j < 4; ++j) {
            float p0 = ex2f(acc[j][0]), p1 = ex2f(acc[j][1]);
            float p2 = ex2f(acc[j][2]), p3 = ex2f(acc[j][3]);
            rs0 += p0 + p1;
            rs1 += p2 + p3;
            __half2 h01 = __floats2half2_rn(p0, p1);
            __half2 h23 = __floats2half2_rn(p2, p3);
            __half2 l01 = __floats2half2_rn(p0 - __low2float(h01), p1 - __high2float(h01));
            __half2 l23 = __floats2half2_rn(p2 - __low2float(h23), p3 - __high2float(h23));
            p01h[j] = *reinterpret_cast<uint32_t*>(&h01);
            p23h[j] = *reinterpret_cast<uint32_t*>(&h23);
            p01l[j] = *reinterpret_cast<uint32_t*>(&l01);
            p23l[j] = *reinterpret_cast<uint32_t*>(&l23);
        }

        // ---- stmatrix P: [128 m][64 k], warp writes m16 x k32 at col half*32 ----
        {
            int g = lane >> 3;
            uint32_t row = ms + (g & 1) * 8 + (lane & 7);
            uint32_t colb = half * 64 + (g >> 1) * 16;
            uint32_t a0 = sb + SPHI + row * P_STR + colb;
            uint32_t a1 = a0 + 32;
            stsm4(a0, p01h[0], p23h[0], p01h[1], p23h[1]);
            stsm4(a1, p01h[2], p23h[2], p01h[3], p23h[3]);
            a0 = sb + SPLO + row * P_STR + colb;
            a1 = a0 + 32;
            stsm4(a0, p01l[0], p23l[0], p01l[1], p23l[1]);
            stsm4(a1, p01l[2], p23l[2], p01l[3], p23l[3]);
        }
        __syncthreads();

        // ---- O += P V (2-term: P split, V single), warp tile m16 x c128 ----
#pragma unroll
        for (int kt = 0; kt < 4; ++kt) {
            uint32_t ah0, ah1, ah2, ah3, al0, al1, al2, al3;
            {
                uint32_t a = sb + SPHI + (ms + (lane & 15)) * P_STR + kt * 32 + (lane >> 4) * 16;
                ldsm4(ah0, ah1, ah2, ah3, a);
                a = sb + SPLO + (ms + (lane & 15)) * P_STR + kt * 32 + (lane >> 4) * 16;
                ldsm4(al0, al1, al2, al3, a);
            }
            uint32_t vrow = kt * 16 + ((lane >> 3) & 1) * 8 + (lane & 7);
#pragma unroll
            for (int blk = 0; blk < 8; ++blk) {
                uint32_t colb = half * 256 + blk * 32 + ((lane >> 4) & 1) * 16;
                uint32_t bh0, bh1, bh2, bh3;
                ldsm4t(bh0, bh1, bh2, bh3, sb + SVBASE(st) + vrow * V_STR + colb);
                int j = blk * 2;
                mma_f16(O[j],     ah0, ah1, ah2, ah3, bh0, bh1);
                mma_f16(O[j],     al0, al1, al2, al3, bh0, bh1);
                mma_f16(O[j + 1], ah0, ah1, ah2, ah3, bh2, bh3);
                mma_f16(O[j + 1], al0, al1, al2, al3, bh2, bh3);
            }
        }
        __syncthreads();
    }

    // ---- epilogue: combine row sums, normalize, store ----
    rs0 += __shfl_xor_sync(0xffffffffu, rs0, 1);
    rs0 += __shfl_xor_sync(0xffffffffu, rs0, 2);
    rs1 += __shfl_xor_sync(0xffffffffu, rs1, 1);
    rs1 += __shfl_xor_sync(0xffffffffu, rs1, 2);
    float* sLp = (float*)(sm + SLP);
    if ((lane & 3) == 0) {
        sLp[half * 128 + ms + (lane >> 2)]     = rs0;
        sLp[half * 128 + ms + (lane >> 2) + 8] = rs1;
    }
    __syncthreads();

    int r0 = ms + (lane >> 2);
    float inv0 = 1.0f / (sLp[r0] + sLp[128 + r0]);
    float inv1 = 1.0f / (sLp[r0 + 8] + sLp[128 + r0 + 8]);

    float* ob = out + (size_t)b * C_IN * N_PIX + m_base;
#pragma unroll
    for (int j = 0; j < 16; ++j) {
        int c = half * 128 + j * 8 + 2 * (lane & 3);
        ob[(size_t)c * N_PIX + r0]           = O[j][0] * inv0;
        ob[(size_t)(c + 1) * N_PIX + r0]     = O[j][1] * inv0;
        ob[(size_t)c * N_PIX + r0 + 8]       = O[j][2] * inv1;
        ob[(size_t)(c + 1) * N_PIX + r0 + 8] = O[j][3] * inv1;
    }
}

// ---------------- launch ----------------
extern "C" void kernel_launch(void* const* d_in, const int* in_sizes, int n_in,
                              void* d_out, int out_size)
{
    const float* x1 = (const float*)d_in[0];
    const float* x2 = (const float*)d_in[1];

    fold_kernel<<<320, 256>>>(
        (const float*)d_in[2],  (const float*)d_in[3],  (const float*)d_in[4],
        (const float*)d_in[5],  (const float*)d_in[6],  (const float*)d_in[7],
        (const float*)d_in[8],  (const float*)d_in[9],  (const float*)d_in[10],
        (const float*)d_in[11], (const float*)d_in[12], (const float*)d_in[13],
        (const float*)d_in[14], (const float*)d_in[15], (const float*)d_in[16],
        (const float*)d_in[17], (const float*)d_in[18], (const float*)d_in[19]);

    proj_kernel<<<dim3(N_PIX / 128, 10, B_SZ), 128>>>(x1, x2);

    cudaFuncSetAttribute(flash_mma, cudaFuncAttributeMaxDynamicSharedMemorySize, SMEM_TOTAL);
    flash_mma<<<dim3(N_PIX / M_TILE, B_SZ), 512, SMEM_TOTAL>>>((float*)d_out);
}

// round 10
// speedup vs baseline: 8.8856x; 1.2423x over previous
#include <cuda_runtime.h>
#include <cuda_fp16.h>
#include <cstdint>

#define N_PIX  4096
#define C_IN   256
#define B_SZ   4
#define TN     64
#define NTILES (N_PIX / TN)
#define M_TILE 128

// smem byte offsets
#define SQHI 0                       // [128 m][32 d] fp16, stride 80
#define SQLO 10240
#define SKBASE(st) (20480 + (st) * 10240)   // hi at +0, lo at +5120; [64 n][32 d]
#define SVBASE(st) (40960 + (st) * 33792)   // [64 n][256 c] fp16 single, stride 528
#define SPHI 108544                  // [128 m][64 k] fp16 single, stride 144
#define SLP  126976                  // 2 x 128 float partial row sums
#define SMEM_TOTAL 128000

#define QK_STR 80
#define P_STR  144
#define V_STR  528

// ---------------- device scratch ----------------
__device__ __align__(16) __half g_Qs[B_SZ * N_PIX * 64];            // [b][m][hi32|lo32], scale*log2e folded
__device__ __align__(16) __half g_Ks[B_SZ * N_PIX * 64];            // [b][n][hi32|lo32]
__device__ __align__(16) __half g_V[(size_t)B_SZ * N_PIX * C_IN];   // [b][n][c] single fp16
__device__ __align__(16) float g_Wf[320 * C_IN];
__device__ float g_Bf[320];

// ---------------- helpers ----------------
__device__ __forceinline__ uint32_t s2u(const void* p) {
    uint32_t a;
    asm("{ .reg .u64 t; cvta.to.shared.u64 t, %1; cvt.u32.u64 %0, t; }" : "=r"(a) : "l"(p));
    return a;
}
__device__ __forceinline__ void cp16(uint32_t dst, const void* src) {
    asm volatile("cp.async.cg.shared.global [%0], [%1], 16;\n" :: "r"(dst), "l"(src));
}
#define CP_COMMIT() asm volatile("cp.async.commit_group;\n" ::: "memory")
#define CP_WAIT0()  asm volatile("cp.async.wait_group 0;\n" ::: "memory")
#define CP_WAIT1()  asm volatile("cp.async.wait_group 1;\n" ::: "memory")

__device__ __forceinline__ void ldsm4(uint32_t& r0, uint32_t& r1, uint32_t& r2, uint32_t& r3, uint32_t a) {
    asm volatile("ldmatrix.sync.aligned.m8n8.x4.shared.b16 {%0,%1,%2,%3}, [%4];"
                 : "=r"(r0), "=r"(r1), "=r"(r2), "=r"(r3) : "r"(a));
}
__device__ __forceinline__ void ldsm4t(uint32_t& r0, uint32_t& r1, uint32_t& r2, uint32_t& r3, uint32_t a) {
    asm volatile("ldmatrix.sync.aligned.m8n8.x4.trans.shared.b16 {%0,%1,%2,%3}, [%4];"
                 : "=r"(r0), "=r"(r1), "=r"(r2), "=r"(r3) : "r"(a));
}
__device__ __forceinline__ void stsm4(uint32_t a, uint32_t r0, uint32_t r1, uint32_t r2, uint32_t r3) {
    asm volatile("stmatrix.sync.aligned.m8n8.x4.shared.b16 [%0], {%1,%2,%3,%4};"
                 :: "r"(a), "r"(r0), "r"(r1), "r"(r2), "r"(r3) : "memory");
}
__device__ __forceinline__ void mma_f16(float* c, uint32_t a0, uint32_t a1, uint32_t a2, uint32_t a3,
                                        uint32_t b0, uint32_t b1) {
    asm volatile(
        "mma.sync.aligned.m16n8k16.row.col.f32.f16.f16.f32 "
        "{%0,%1,%2,%3}, {%4,%5,%6,%7}, {%8,%9}, {%0,%1,%2,%3};"
        : "+f"(c[0]), "+f"(c[1]), "+f"(c[2]), "+f"(c[3])
        : "r"(a0), "r"(a1), "r"(a2), "r"(a3), "r"(b0), "r"(b1));
}
__device__ __forceinline__ float ex2f(float x) {
    float e; asm("ex2.approx.ftz.f32 %0, %1;" : "=f"(e) : "f"(x)); return e;
}

__device__ __forceinline__ unsigned long long pack2(float x, float y) {
    unsigned long long r;
    asm("mov.b64 %0, {%1, %2};" : "=l"(r) : "f"(x), "f"(y));
    return r;
}
__device__ __forceinline__ unsigned long long dup2(float x) { return pack2(x, x); }
__device__ __forceinline__ unsigned long long ffma2(unsigned long long a, unsigned long long b,
                                                    unsigned long long c) {
    unsigned long long d;
    asm("fma.rn.f32x2 %0, %1, %2, %3;" : "=l"(d) : "l"(a), "l"(b), "l"(c));
    return d;
}
__device__ __forceinline__ void unpack2(unsigned long long v, float& x, float& y) {
    asm("mov.b64 {%0, %1}, %2;" : "=f"(x), "=f"(y) : "l"(v));
}

// ---------------- fold BN into 1x1-conv weights ----------------
__global__ void fold_kernel(
    const float* __restrict__ qw, const float* __restrict__ qb,
    const float* __restrict__ qg, const float* __restrict__ qbe,
    const float* __restrict__ qm, const float* __restrict__ qv,
    const float* __restrict__ kw, const float* __restrict__ kb,
    const float* __restrict__ kg, const float* __restrict__ kbe,
    const float* __restrict__ km, const float* __restrict__ kv,
    const float* __restrict__ vw, const float* __restrict__ vb,
    const float* __restrict__ vg, const float* __restrict__ vbe,
    const float* __restrict__ vm, const float* __restrict__ vv)
{
    int r = blockIdx.x;
    const float *w, *bb, *g, *be, *mn, *vr; int j;
    if (r < 32)      { w = qw; bb = qb; g = qg; be = qbe; mn = qm; vr = qv; j = r; }
    else if (r < 64) { w = kw; bb = kb; g = kg; be = kbe; mn = km; vr = kv; j = r - 32; }
    else             { w = vw; bb = vb; g = vg; be = vbe; mn = vm; vr = vv; j = r - 64; }
    float inv = g[j] * rsqrtf(vr[j] + 1e-5f);
    int c = threadIdx.x;
    g_Wf[r * C_IN + c] = w[j * C_IN + c] * inv;
    if (c == 0) g_Bf[r] = bb[j] * inv + be[j] - mn[j] * inv;
}

// ---------------- projection -> fp16 operands ----------------
// grid: (N_PIX/128, 10 segs, B). seg 0 -> Q(x1), 1 -> K(x2), 2-9 -> V(x2)
__global__ __launch_bounds__(128) void proj_kernel(
    const float* __restrict__ x1, const float* __restrict__ x2)
{
    __shared__ float2 sW2[C_IN * 16];
    int seg = blockIdx.y, b = blockIdx.z;
    int tid = threadIdx.x;
    int n = blockIdx.x * 128 + tid;
    int r0 = seg * 32;
    for (int i = tid; i < C_IN * 16; i += 128) {
        int c = i >> 4, dp = i & 15;
        sW2[i] = make_float2(g_Wf[(r0 + 2 * dp) * C_IN + c],
                             g_Wf[(r0 + 2 * dp + 1) * C_IN + c]);
    }
    __syncthreads();

    const float* x  = (seg == 0) ? x1 : x2;
    const float* xb = x + (size_t)b * C_IN * N_PIX + n;

    unsigned long long acc2[16];
#pragma unroll
    for (int dp = 0; dp < 16; ++dp) acc2[dp] = 0ull;

#pragma unroll 2
    for (int c = 0; c < C_IN; c += 4) {
        float xv[4];
#pragma unroll
        for (int u = 0; u < 4; ++u) xv[u] = xb[(c + u) * N_PIX];
#pragma unroll
        for (int u = 0; u < 4; ++u) {
            unsigned long long xd = dup2(xv[u]);
            const ulonglong2* wr = (const ulonglong2*)&sW2[(c + u) * 16];
#pragma unroll
            for (int q = 0; q < 8; ++q) {
                ulonglong2 w = wr[q];
                acc2[2 * q]     = ffma2(w.x, xd, acc2[2 * q]);
                acc2[2 * q + 1] = ffma2(w.y, xd, acc2[2 * q + 1]);
            }
        }
    }

    float f[32];
#pragma unroll
    for (int dp = 0; dp < 16; ++dp) unpack2(acc2[dp], f[2 * dp], f[2 * dp + 1]);
#pragma unroll
    for (int d = 0; d < 32; ++d) f[d] += g_Bf[r0 + d];

    if (seg == 0) {
        const float qs = 0.17677669529663689f * 1.4426950408889634f;  // scale * log2(e)
#pragma unroll
        for (int d = 0; d < 32; ++d) f[d] *= qs;
    }

    if (seg < 2) {
        // hi/lo fp16 split; row: [hi 32 fp16 | lo 32 fp16] = 128B
        uint32_t uh[16], ul[16];
#pragma unroll
        for (int j = 0; j < 16; ++j) {
            float a = f[2 * j], c = f[2 * j + 1];
            __half2 h2 = __floats2half2_rn(a, c);
            float ra = a - __low2float(h2);
            float rc = c - __high2float(h2);
            __half2 l2 = __floats2half2_rn(ra, rc);
            uh[j] = *reinterpret_cast<uint32_t*>(&h2);
            ul[j] = *reinterpret_cast<uint32_t*>(&l2);
        }
        char* dst = (char*)((seg == 0) ? g_Qs : g_Ks) + ((size_t)(b * N_PIX + n)) * 128;
#pragma unroll
        for (int q = 0; q < 4; ++q) {
            *(uint4*)(dst + q * 16)      = make_uint4(uh[4 * q], uh[4 * q + 1], uh[4 * q + 2], uh[4 * q + 3]);
            *(uint4*)(dst + 64 + q * 16) = make_uint4(ul[4 * q], ul[4 * q + 1], ul[4 * q + 2], ul[4 * q + 3]);
        }
    } else {
        // V: single fp16
        int c0 = (seg - 2) * 32;
        uint32_t uh[16];
#pragma unroll
        for (int j = 0; j < 16; ++j) {
            __half2 h2 = __floats2half2_rn(f[2 * j], f[2 * j + 1]);
            uh[j] = *reinterpret_cast<uint32_t*>(&h2);
        }
        char* dh = (char*)g_V + (((size_t)(b * N_PIX + n)) * C_IN + c0) * 2;
#pragma unroll
        for (int q = 0; q < 4; ++q)
            *(uint4*)(dh + q * 16) = make_uint4(uh[4 * q], uh[4 * q + 1], uh[4 * q + 2], uh[4 * q + 3]);
    }
}

// ---------------- flash attention: fp16 mma.sync, 2-stage pipeline, P single ----------------
// grid: (N_PIX/128, B), 512 threads = 16 warps, occ 1.
// S phase:  warp w -> m-slice (w&7)*16, n-half (w>>3)*32
// PV phase: warp w -> m-slice (w&7)*16, c-half (w>>3)*128
__global__ __launch_bounds__(512, 1) void flash_mma(float* __restrict__ out)
{
    extern __shared__ __align__(16) char sm[];
    const uint32_t sb = s2u(sm);
    const int tid  = threadIdx.x;
    const int warp = tid >> 5;
    const int lane = tid & 31;
    const int ms   = (warp & 7) * 16;
    const int half = warp >> 3;
    const int b    = blockIdx.y;
    const int m_base = blockIdx.x * M_TILE;

    const char* gkb = (const char*)g_Ks + ((size_t)b * N_PIX) * 128;
    const char* gvb = (const char*)g_V + ((size_t)b * N_PIX) * C_IN * 2;

    // ---- Q tiles (persistent) ----
    {
        const char* gq = (const char*)g_Qs + ((size_t)(b * N_PIX + m_base)) * 128;
        for (int i = tid; i < 1024; i += 512) {
            int m = i >> 3, q = i & 7;
            uint4 v = *(const uint4*)(gq + (size_t)m * 128 + q * 16);
            if (q < 4) *(uint4*)(sm + SQHI + m * QK_STR + q * 16) = v;
            else       *(uint4*)(sm + SQLO + m * QK_STR + (q - 4) * 16) = v;
        }
    }

    float O[16][4];
#pragma unroll
    for (int j = 0; j < 16; ++j)
#pragma unroll
        for (int k = 0; k < 4; ++k) O[j][k] = 0.f;
    float rs0 = 0.f, rs1 = 0.f;

    // ---- tile loader (cp.async) ----
    auto load_kv = [&](int t, int st) {
        const char* gk = gkb + (size_t)t * TN * 128;
        {
            int n = tid >> 3, q = tid & 7;
            uint32_t d = (q < 4) ? (sb + SKBASE(st) + n * QK_STR + q * 16)
                                 : (sb + SKBASE(st) + 5120 + n * QK_STR + (q - 4) * 16);
            cp16(d, gk + (size_t)n * 128 + q * 16);
        }
        const char* gv = gvb + (size_t)t * TN * C_IN * 2;
        for (int i = tid; i < 2048; i += 512) {
            int n = i >> 5, q = i & 31;
            cp16(sb + SVBASE(st) + n * V_STR + q * 16, gv + (size_t)n * 512 + q * 16);
        }
    };

    load_kv(0, 0);
    CP_COMMIT();

#pragma unroll 1
    for (int t = 0; t < NTILES; ++t) {
        const int st = t & 1;
        if (t + 1 < NTILES) {
            load_kv(t + 1, st ^ 1);
            CP_COMMIT();
            CP_WAIT1();
        } else {
            CP_WAIT0();
        }
        __syncthreads();

        // ---- S = Q K^T (3-term fp16 hi/lo), warp tile m16 x n32 ----
        float acc[4][4];
#pragma unroll
        for (int j = 0; j < 4; ++j)
#pragma unroll
            for (int k = 0; k < 4; ++k) acc[j][k] = 0.f;

#pragma unroll
        for (int kt = 0; kt < 2; ++kt) {
            uint32_t ah0, ah1, ah2, ah3, al0, al1, al2, al3;
            {
                uint32_t a = sb + SQHI + (ms + (lane & 15)) * QK_STR + kt * 32 + (lane >> 4) * 16;
                ldsm4(ah0, ah1, ah2, ah3, a);
                a = sb + SQLO + (ms + (lane & 15)) * QK_STR + kt * 32 + (lane >> 4) * 16;
                ldsm4(al0, al1, al2, al3, a);
            }
#pragma unroll
            for (int nb = 0; nb < 2; ++nb) {
                int nbase = half * 32 + nb * 16;
                uint32_t row = nbase + ((lane >> 4) << 3) + (lane & 7);
                uint32_t col = kt * 32 + ((lane >> 3) & 1) * 16;
                uint32_t bh0, bh1, bh2, bh3, bl0, bl1, bl2, bl3;
                ldsm4(bh0, bh1, bh2, bh3, sb + SKBASE(st) + row * QK_STR + col);
                ldsm4(bl0, bl1, bl2, bl3, sb + SKBASE(st) + 5120 + row * QK_STR + col);
                mma_f16(acc[2 * nb],     ah0, ah1, ah2, ah3, bh0, bh1);
                mma_f16(acc[2 * nb],     ah0, ah1, ah2, ah3, bl0, bl1);
                mma_f16(acc[2 * nb],     al0, al1, al2, al3, bh0, bh1);
                mma_f16(acc[2 * nb + 1], ah0, ah1, ah2, ah3, bh2, bh3);
                mma_f16(acc[2 * nb + 1], ah0, ah1, ah2, ah3, bl2, bl3);
                mma_f16(acc[2 * nb + 1], al0, al1, al2, al3, bh2, bh3);
            }
        }

        // ---- P = exp2(S) unnormalized; row sums; pack fp16 single ----
        uint32_t p01h[4], p23h[4];
#pragma unroll
        for (int j = 0; j < 4; ++j) {
            float p0 = ex2f(acc[j][0]), p1 = ex2f(acc[j][1]);
            float p2 = ex2f(acc[j][2]), p3 = ex2f(acc[j][3]);
            rs0 += p0 + p1;
            rs1 += p2 + p3;
            __half2 h01 = __floats2half2_rn(p0, p1);
            __half2 h23 = __floats2half2_rn(p2, p3);
            p01h[j] = *reinterpret_cast<uint32_t*>(&h01);
            p23h[j] = *reinterpret_cast<uint32_t*>(&h23);
        }

        // ---- stmatrix P: [128 m][64 k], warp writes m16 x k32 at col half*32 ----
        {
            int g = lane >> 3;
            uint32_t row = ms + (g & 1) * 8 + (lane & 7);
            uint32_t colb = half * 64 + (g >> 1) * 16;
            uint32_t a0 = sb + SPHI + row * P_STR + colb;
            uint32_t a1 = a0 + 32;
            stsm4(a0, p01h[0], p23h[0], p01h[1], p23h[1]);
            stsm4(a1, p01h[2], p23h[2], p01h[3], p23h[3]);
        }
        __syncthreads();

        // ---- O += P V (single-term), warp tile m16 x c128 ----
#pragma unroll
        for (int kt = 0; kt < 4; ++kt) {
            uint32_t ah0, ah1, ah2, ah3;
            {
                uint32_t a = sb + SPHI + (ms + (lane & 15)) * P_STR + kt * 32 + (lane >> 4) * 16;
                ldsm4(ah0, ah1, ah2, ah3, a);
            }
            uint32_t vrow = kt * 16 + ((lane >> 3) & 1) * 8 + (lane & 7);
#pragma unroll
            for (int blk = 0; blk < 8; ++blk) {
                uint32_t colb = half * 256 + blk * 32 + ((lane >> 4) & 1) * 16;
                uint32_t bh0, bh1, bh2, bh3;
                ldsm4t(bh0, bh1, bh2, bh3, sb + SVBASE(st) + vrow * V_STR + colb);
                int j = blk * 2;
                mma_f16(O[j],     ah0, ah1, ah2, ah3, bh0, bh1);
                mma_f16(O[j + 1], ah0, ah1, ah2, ah3, bh2, bh3);
            }
        }
        __syncthreads();
    }

    // ---- epilogue: combine row sums, normalize, store ----
    rs0 += __shfl_xor_sync(0xffffffffu, rs0, 1);
    rs0 += __shfl_xor_sync(0xffffffffu, rs0, 2);
    rs1 += __shfl_xor_sync(0xffffffffu, rs1, 1);
    rs1 += __shfl_xor_sync(0xffffffffu, rs1, 2);
    float* sLp = (float*)(sm + SLP);
    if ((lane & 3) == 0) {
        sLp[half * 128 + ms + (lane >> 2)]     = rs0;
        sLp[half * 128 + ms + (lane >> 2) + 8] = rs1;
    }
    __syncthreads();

    int r0 = ms + (lane >> 2);
    float inv0 = 1.0f / (sLp[r0] + sLp[128 + r0]);
    float inv1 = 1.0f / (sLp[r0 + 8] + sLp[128 + r0 + 8]);

    float* ob = out + (size_t)b * C_IN * N_PIX + m_base;
#pragma unroll
    for (int j = 0; j < 16; ++j) {
        int c = half * 128 + j * 8 + 2 * (lane & 3);
        ob[(size_t)c * N_PIX + r0]           = O[j][0] * inv0;
        ob[(size_t)(c + 1) * N_PIX + r0]     = O[j][1] * inv0;
        ob[(size_t)c * N_PIX + r0 + 8]       = O[j][2] * inv1;
        ob[(size_t)(c + 1) * N_PIX + r0 + 8] = O[j][3] * inv1;
    }
}

// ---------------- launch ----------------
extern "C" void kernel_launch(void* const* d_in, const int* in_sizes, int n_in,
                              void* d_out, int out_size)
{
    const float* x1 = (const float*)d_in[0];
    const float* x2 = (const float*)d_in[1];

    fold_kernel<<<320, 256>>>(
        (const float*)d_in[2],  (const float*)d_in[3],  (const float*)d_in[4],
        (const float*)d_in[5],  (const float*)d_in[6],  (const float*)d_in[7],
        (const float*)d_in[8],  (const float*)d_in[9],  (const float*)d_in[10],
        (const float*)d_in[11], (const float*)d_in[12], (const float*)d_in[13],
        (const float*)d_in[14], (const float*)d_in[15], (const float*)d_in[16],
        (const float*)d_in[17], (const float*)d_in[18], (const float*)d_in[19]);

    proj_kernel<<<dim3(N_PIX / 128, 10, B_SZ), 128>>>(x1, x2);

    cudaFuncSetAttribute(flash_mma, cudaFuncAttributeMaxDynamicSharedMemorySize, SMEM_TOTAL);
    flash_mma<<<dim3(N_PIX / M_TILE, B_SZ), 512, SMEM_TOTAL>>>((float*)d_out);
}

// round 11
// speedup vs baseline: 10.1384x; 1.1410x over previous
#include <cuda_runtime.h>
#include <cuda_fp16.h>
#include <cstdint>

#define N_PIX  4096
#define C_IN   256
#define B_SZ   4
#define TN     128
#define NTILES (N_PIX / TN)     // 32
#define M_TILE 128

// smem byte offsets
#define SQHI 0                          // [128 m][32 d] fp16, stride 80
#define SQLO 10240
#define SKB(st) (20480 + (st) * 20480)  // hi +0, lo +10240; [128 n][32 d]
#define SV   61440                      // [128 n][256 c] fp16 single stage, stride 528
#define SP   129024                     // [128 m][128 k] fp16 single, stride 272
#define SLP  163840                     // 2 x 128 float partial row sums
#define SMEM_TOTAL 164864

#define QK_STR 80
#define P_STR  272
#define V_STR  528

// ---------------- device scratch ----------------
__device__ __align__(16) __half g_Qs[B_SZ * N_PIX * 64];            // [b][m][hi32|lo32], scale*log2e folded
__device__ __align__(16) __half g_Ks[B_SZ * N_PIX * 64];            // [b][n][hi32|lo32]
__device__ __align__(16) __half g_V[(size_t)B_SZ * N_PIX * C_IN];   // [b][n][c] single fp16
__device__ __align__(16) float g_Wf[320 * C_IN];
__device__ float g_Bf[320];

// ---------------- helpers ----------------
__device__ __forceinline__ uint32_t s2u(const void* p) {
    uint32_t a;
    asm("{ .reg .u64 t; cvta.to.shared.u64 t, %1; cvt.u32.u64 %0, t; }" : "=r"(a) : "l"(p));
    return a;
}
__device__ __forceinline__ void cp16(uint32_t dst, const void* src) {
    asm volatile("cp.async.cg.shared.global [%0], [%1], 16;\n" :: "r"(dst), "l"(src));
}
#define CP_COMMIT() asm volatile("cp.async.commit_group;\n" ::: "memory")
#define CP_WAITN(n) asm volatile("cp.async.wait_group %0;\n" :: "n"(n) : "memory")

__device__ __forceinline__ void ldsm4(uint32_t& r0, uint32_t& r1, uint32_t& r2, uint32_t& r3, uint32_t a) {
    asm volatile("ldmatrix.sync.aligned.m8n8.x4.shared.b16 {%0,%1,%2,%3}, [%4];"
                 : "=r"(r0), "=r"(r1), "=r"(r2), "=r"(r3) : "r"(a));
}
__device__ __forceinline__ void ldsm4t(uint32_t& r0, uint32_t& r1, uint32_t& r2, uint32_t& r3, uint32_t a) {
    asm volatile("ldmatrix.sync.aligned.m8n8.x4.trans.shared.b16 {%0,%1,%2,%3}, [%4];"
                 : "=r"(r0), "=r"(r1), "=r"(r2), "=r"(r3) : "r"(a));
}
__device__ __forceinline__ void stsm4(uint32_t a, uint32_t r0, uint32_t r1, uint32_t r2, uint32_t r3) {
    asm volatile("stmatrix.sync.aligned.m8n8.x4.shared.b16 [%0], {%1,%2,%3,%4};"
                 :: "r"(a), "r"(r0), "r"(r1), "r"(r2), "r"(r3) : "memory");
}
__device__ __forceinline__ void mma_f16(float* c, uint32_t a0, uint32_t a1, uint32_t a2, uint32_t a3,
                                        uint32_t b0, uint32_t b1) {
    asm volatile(
        "mma.sync.aligned.m16n8k16.row.col.f32.f16.f16.f32 "
        "{%0,%1,%2,%3}, {%4,%5,%6,%7}, {%8,%9}, {%0,%1,%2,%3};"
        : "+f"(c[0]), "+f"(c[1]), "+f"(c[2]), "+f"(c[3])
        : "r"(a0), "r"(a1), "r"(a2), "r"(a3), "r"(b0), "r"(b1));
}
__device__ __forceinline__ float ex2f(float x) {
    float e; asm("ex2.approx.ftz.f32 %0, %1;" : "=f"(e) : "f"(x)); return e;
}

__device__ __forceinline__ unsigned long long pack2(float x, float y) {
    unsigned long long r;
    asm("mov.b64 %0, {%1, %2};" : "=l"(r) : "f"(x), "f"(y));
    return r;
}
__device__ __forceinline__ unsigned long long dup2(float x) { return pack2(x, x); }
__device__ __forceinline__ unsigned long long ffma2(unsigned long long a, unsigned long long b,
                                                    unsigned long long c) {
    unsigned long long d;
    asm("fma.rn.f32x2 %0, %1, %2, %3;" : "=l"(d) : "l"(a), "l"(b), "l"(c));
    return d;
}
__device__ __forceinline__ void unpack2(unsigned long long v, float& x, float& y) {
    asm("mov.b64 {%0, %1}, %2;" : "=f"(x), "=f"(y) : "l"(v));
}

// ---------------- fold BN into 1x1-conv weights ----------------
__global__ void fold_kernel(
    const float* __restrict__ qw, const float* __restrict__ qb,
    const float* __restrict__ qg, const float* __restrict__ qbe,
    const float* __restrict__ qm, const float* __restrict__ qv,
    const float* __restrict__ kw, const float* __restrict__ kb,
    const float* __restrict__ kg, const float* __restrict__ kbe,
    const float* __restrict__ km, const float* __restrict__ kv,
    const float* __restrict__ vw, const float* __restrict__ vb,
    const float* __restrict__ vg, const float* __restrict__ vbe,
    const float* __restrict__ vm, const float* __restrict__ vv)
{
    int r = blockIdx.x;
    const float *w, *bb, *g, *be, *mn, *vr; int j;
    if (r < 32)      { w = qw; bb = qb; g = qg; be = qbe; mn = qm; vr = qv; j = r; }
    else if (r < 64) { w = kw; bb = kb; g = kg; be = kbe; mn = km; vr = kv; j = r - 32; }
    else             { w = vw; bb = vb; g = vg; be = vbe; mn = vm; vr = vv; j = r - 64; }
    float inv = g[j] * rsqrtf(vr[j] + 1e-5f);
    int c = threadIdx.x;
    g_Wf[r * C_IN + c] = w[j * C_IN + c] * inv;
    if (c == 0) g_Bf[r] = bb[j] * inv + be[j] - mn[j] * inv;
}

// ---------------- projection -> fp16 operands (2 pixels per thread) ----------------
// grid: (N_PIX/256, 10 segs, B). seg 0 -> Q(x1), 1 -> K(x2), 2-9 -> V(x2)
__global__ __launch_bounds__(128) void proj_kernel(
    const float* __restrict__ x1, const float* __restrict__ x2)
{
    __shared__ float2 sW2[C_IN * 16];
    int seg = blockIdx.y, b = blockIdx.z;
    int tid = threadIdx.x;
    int n = blockIdx.x * 256 + tid;        // pixel A; pixel B = n + 128
    int r0 = seg * 32;
    for (int i = tid; i < C_IN * 16; i += 128) {
        int c = i >> 4, dp = i & 15;
        sW2[i] = make_float2(g_Wf[(r0 + 2 * dp) * C_IN + c],
                             g_Wf[(r0 + 2 * dp + 1) * C_IN + c]);
    }
    __syncthreads();

    const float* x  = (seg == 0) ? x1 : x2;
    const float* xa = x + (size_t)b * C_IN * N_PIX + n;
    const float* xc = xa + 128;

    unsigned long long accA[16], accB[16];
#pragma unroll
    for (int dp = 0; dp < 16; ++dp) { accA[dp] = 0ull; accB[dp] = 0ull; }

#pragma unroll 2
    for (int c = 0; c < C_IN; c += 4) {
        float xva[4], xvb[4];
#pragma unroll
        for (int u = 0; u < 4; ++u) { xva[u] = xa[(c + u) * N_PIX]; xvb[u] = xc[(c + u) * N_PIX]; }
#pragma unroll
        for (int u = 0; u < 4; ++u) {
            unsigned long long xdA = dup2(xva[u]);
            unsigned long long xdB = dup2(xvb[u]);
            const ulonglong2* wr = (const ulonglong2*)&sW2[(c + u) * 16];
#pragma unroll
            for (int q = 0; q < 8; ++q) {
                ulonglong2 w = wr[q];
                accA[2 * q]     = ffma2(w.x, xdA, accA[2 * q]);
                accA[2 * q + 1] = ffma2(w.y, xdA, accA[2 * q + 1]);
                accB[2 * q]     = ffma2(w.x, xdB, accB[2 * q]);
                accB[2 * q + 1] = ffma2(w.y, xdB, accB[2 * q + 1]);
            }
        }
    }

#pragma unroll
    for (int px = 0; px < 2; ++px) {
        const unsigned long long* acc2 = (px == 0) ? accA : accB;
        int np = n + px * 128;
        float f[32];
#pragma unroll
        for (int dp = 0; dp < 16; ++dp) unpack2(acc2[dp], f[2 * dp], f[2 * dp + 1]);
#pragma unroll
        for (int d = 0; d < 32; ++d) f[d] += g_Bf[r0 + d];

        if (seg == 0) {
            const float qs = 0.17677669529663689f * 1.4426950408889634f;  // scale * log2(e)
#pragma unroll
            for (int d = 0; d < 32; ++d) f[d] *= qs;
        }

        if (seg < 2) {
            uint32_t uh[16], ul[16];
#pragma unroll
            for (int j = 0; j < 16; ++j) {
                float a = f[2 * j], c = f[2 * j + 1];
                __half2 h2 = __floats2half2_rn(a, c);
                float ra = a - __low2float(h2);
                float rc = c - __high2float(h2);
                __half2 l2 = __floats2half2_rn(ra, rc);
                uh[j] = *reinterpret_cast<uint32_t*>(&h2);
                ul[j] = *reinterpret_cast<uint32_t*>(&l2);
            }
            char* dst = (char*)((seg == 0) ? g_Qs : g_Ks) + ((size_t)(b * N_PIX + np)) * 128;
#pragma unroll
            for (int q = 0; q < 4; ++q) {
                *(uint4*)(dst + q * 16)      = make_uint4(uh[4 * q], uh[4 * q + 1], uh[4 * q + 2], uh[4 * q + 3]);
                *(uint4*)(dst + 64 + q * 16) = make_uint4(ul[4 * q], ul[4 * q + 1], ul[4 * q + 2], ul[4 * q + 3]);
            }
        } else {
            int c0 = (seg - 2) * 32;
            uint32_t uh[16];
#pragma unroll
            for (int j = 0; j < 16; ++j) {
                __half2 h2 = __floats2half2_rn(f[2 * j], f[2 * j + 1]);
                uh[j] = *reinterpret_cast<uint32_t*>(&h2);
            }
            char* dh = (char*)g_V + (((size_t)(b * N_PIX + np)) * C_IN + c0) * 2;
#pragma unroll
            for (int q = 0; q < 4; ++q)
                *(uint4*)(dh + q * 16) = make_uint4(uh[4 * q], uh[4 * q + 1], uh[4 * q + 2], uh[4 * q + 3]);
        }
    }
}

// ---------------- flash attention: fp16 mma.sync, TN=128, K dbl-buf + V single-buf ----------------
// grid: (N_PIX/128, B), 512 threads = 16 warps, occ 1.
// S phase:  warp w -> m-slice (w&7)*16, n-half (w>>3)*64 (two n32 sub-passes)
// PV phase: warp w -> m-slice (w&7)*16, c-half (w>>3)*128
__global__ __launch_bounds__(512, 1) void flash_mma(float* __restrict__ out)
{
    extern __shared__ __align__(16) char sm[];
    const uint32_t sb = s2u(sm);
    const int tid  = threadIdx.x;
    const int warp = tid >> 5;
    const int lane = tid & 31;
    const int ms   = (warp & 7) * 16;
    const int half = warp >> 3;
    const int b    = blockIdx.y;
    const int m_base = blockIdx.x * M_TILE;

    const char* gkb = (const char*)g_Ks + ((size_t)b * N_PIX) * 128;
    const char* gvb = (const char*)g_V + ((size_t)b * N_PIX) * C_IN * 2;

    // ---- Q tiles (persistent, plain stores) ----
    {
        const char* gq = (const char*)g_Qs + ((size_t)(b * N_PIX + m_base)) * 128;
        for (int i = tid; i < 1024; i += 512) {
            int m = i >> 3, q = i & 7;
            uint4 v = *(const uint4*)(gq + (size_t)m * 128 + q * 16);
            if (q < 4) *(uint4*)(sm + SQHI + m * QK_STR + q * 16) = v;
            else       *(uint4*)(sm + SQLO + m * QK_STR + (q - 4) * 16) = v;
        }
    }

    float O[16][4];
#pragma unroll
    for (int j = 0; j < 16; ++j)
#pragma unroll
        for (int k = 0; k < 4; ++k) O[j][k] = 0.f;
    float rs0 = 0.f, rs1 = 0.f;

    auto load_k = [&](int t, int st) {
        const char* gk = gkb + (size_t)t * TN * 128;
        for (int i = tid; i < 1024; i += 512) {
            int n = i >> 3, q = i & 7;
            uint32_t d = (q < 4) ? (sb + SKB(st) + n * QK_STR + q * 16)
                                 : (sb + SKB(st) + 10240 + n * QK_STR + (q - 4) * 16);
            cp16(d, gk + (size_t)n * 128 + q * 16);
        }
    };
    auto load_v = [&](int t) {
        const char* gv = gvb + (size_t)t * TN * C_IN * 2;
        for (int i = tid; i < 4096; i += 512) {
            int n = i >> 5, q = i & 31;
            cp16(sb + SV + n * V_STR + q * 16, gv + (size_t)n * 512 + q * 16);
        }
    };

    // prologue: K(0), V(0)
    load_k(0, 0);
    CP_COMMIT();
    load_v(0);
    CP_COMMIT();

#pragma unroll 1
    for (int t = 0; t < NTILES; ++t) {
        const int st = t & 1;
        // prefetch K(t+1)
        if (t + 1 < NTILES) {
            load_k(t + 1, st ^ 1);
            CP_COMMIT();
            CP_WAITN(2);   // K(t) done; V(t), K(t+1) may be in flight
        } else {
            CP_WAITN(1);   // K(t) done; V(t) may be in flight
        }
        __syncthreads();

        // ---- S = Q K^T (3-term fp16 hi/lo), two n32 sub-passes ----
#pragma unroll
        for (int np = 0; np < 2; ++np) {
            float acc[4][4];
#pragma unroll
            for (int j = 0; j < 4; ++j)
#pragma unroll
                for (int k = 0; k < 4; ++k) acc[j][k] = 0.f;

#pragma unroll
            for (int kt = 0; kt < 2; ++kt) {
                uint32_t ah0, ah1, ah2, ah3, al0, al1, al2, al3;
                {
                    uint32_t a = sb + SQHI + (ms + (lane & 15)) * QK_STR + kt * 32 + (lane >> 4) * 16;
                    ldsm4(ah0, ah1, ah2, ah3, a);
                    a = sb + SQLO + (ms + (lane & 15)) * QK_STR + kt * 32 + (lane >> 4) * 16;
                    ldsm4(al0, al1, al2, al3, a);
                }
#pragma unroll
                for (int nb = 0; nb < 2; ++nb) {
                    int nbase = half * 64 + np * 32 + nb * 16;
                    uint32_t row = nbase + ((lane >> 4) << 3) + (lane & 7);
                    uint32_t col = kt * 32 + ((lane >> 3) & 1) * 16;
                    uint32_t bh0, bh1, bh2, bh3, bl0, bl1, bl2, bl3;
                    ldsm4(bh0, bh1, bh2, bh3, sb + SKB(st) + row * QK_STR + col);
                    ldsm4(bl0, bl1, bl2, bl3, sb + SKB(st) + 10240 + row * QK_STR + col);
                    mma_f16(acc[2 * nb],     ah0, ah1, ah2, ah3, bh0, bh1);
                    mma_f16(acc[2 * nb],     ah0, ah1, ah2, ah3, bl0, bl1);
                    mma_f16(acc[2 * nb],     al0, al1, al2, al3, bh0, bh1);
                    mma_f16(acc[2 * nb + 1], ah0, ah1, ah2, ah3, bh2, bh3);
                    mma_f16(acc[2 * nb + 1], ah0, ah1, ah2, ah3, bl2, bl3);
                    mma_f16(acc[2 * nb + 1], al0, al1, al2, al3, bh2, bh3);
                }
            }

            // P = exp2(S) unnormalized; row sums; pack fp16 single
            uint32_t p01h[4], p23h[4];
#pragma unroll
            for (int j = 0; j < 4; ++j) {
                float p0 = ex2f(acc[j][0]), p1 = ex2f(acc[j][1]);
                float p2 = ex2f(acc[j][2]), p3 = ex2f(acc[j][3]);
                rs0 += p0 + p1;
                rs1 += p2 + p3;
                __half2 h01 = __floats2half2_rn(p0, p1);
                __half2 h23 = __floats2half2_rn(p2, p3);
                p01h[j] = *reinterpret_cast<uint32_t*>(&h01);
                p23h[j] = *reinterpret_cast<uint32_t*>(&h23);
            }

            // stmatrix P: [128 m][128 k], warp writes m16 x k32 at col half*128 + np*64
            int g = lane >> 3;
            uint32_t row = ms + (g & 1) * 8 + (lane & 7);
            uint32_t colb = half * 128 + np * 64 + (g >> 1) * 16;
            uint32_t a0 = sb + SP + row * P_STR + colb;
            stsm4(a0,      p01h[0], p23h[0], p01h[1], p23h[1]);
            stsm4(a0 + 32, p01h[2], p23h[2], p01h[3], p23h[3]);
        }

        // ---- wait V(t), then PV ----
        if (t + 1 < NTILES) CP_WAITN(1);   // V(t) done; K(t+1) may be in flight
        else                CP_WAITN(0);
        __syncthreads();

#pragma unroll
        for (int kt = 0; kt < 8; ++kt) {
            uint32_t ah0, ah1, ah2, ah3;
            {
                uint32_t a = sb + SP + (ms + (lane & 15)) * P_STR + kt * 32 + (lane >> 4) * 16;
                ldsm4(ah0, ah1, ah2, ah3, a);
            }
            uint32_t vrow = kt * 16 + ((lane >> 3) & 1) * 8 + (lane & 7);
#pragma unroll
            for (int blk = 0; blk < 8; ++blk) {
                uint32_t colb = half * 256 + blk * 32 + ((lane >> 4) & 1) * 16;
                uint32_t bh0, bh1, bh2, bh3;
                ldsm4t(bh0, bh1, bh2, bh3, sb + SV + vrow * V_STR + colb);
                int j = blk * 2;
                mma_f16(O[j],     ah0, ah1, ah2, ah3, bh0, bh1);
                mma_f16(O[j + 1], ah0, ah1, ah2, ah3, bh2, bh3);
            }
        }
        __syncthreads();

        // ---- issue V(t+1) (overlaps next tile's S phase) ----
        if (t + 1 < NTILES) {
            load_v(t + 1);
            CP_COMMIT();
        }
    }

    // ---- epilogue: combine row sums, normalize, store ----
    rs0 += __shfl_xor_sync(0xffffffffu, rs0, 1);
    rs0 += __shfl_xor_sync(0xffffffffu, rs0, 2);
    rs1 += __shfl_xor_sync(0xffffffffu, rs1, 1);
    rs1 += __shfl_xor_sync(0xffffffffu, rs1, 2);
    float* sLp = (float*)(sm + SLP);
    if ((lane & 3) == 0) {
        sLp[half * 128 + ms + (lane >> 2)]     = rs0;
        sLp[half * 128 + ms + (lane >> 2) + 8] = rs1;
    }
    __syncthreads();

    int r0 = ms + (lane >> 2);
    float inv0 = 1.0f / (sLp[r0] + sLp[128 + r0]);
    float inv1 = 1.0f / (sLp[r0 + 8] + sLp[128 + r0 + 8]);

    float* ob = out + (size_t)b * C_IN * N_PIX + m_base;
#pragma unroll
    for (int j = 0; j < 16; ++j) {
        int c = half * 128 + j * 8 + 2 * (lane & 3);
        ob[(size_t)c * N_PIX + r0]           = O[j][0] * inv0;
        ob[(size_t)(c + 1) * N_PIX + r0]     = O[j][1] * inv0;
        ob[(size_t)c * N_PIX + r0 + 8]       = O[j][2] * inv1;
        ob[(size_t)(c + 1) * N_PIX + r0 + 8] = O[j][3] * inv1;
    }
}

// ---------------- launch ----------------
extern "C" void kernel_launch(void* const* d_in, const int* in_sizes, int n_in,
                              void* d_out, int out_size)
{
    const float* x1 = (const float*)d_in[0];
    const float* x2 = (const float*)d_in[1];

    fold_kernel<<<320, 256>>>(
        (const float*)d_in[2],  (const float*)d_in[3],  (const float*)d_in[4],
        (const float*)d_in[5],  (const float*)d_in[6],  (const float*)d_in[7],
        (const float*)d_in[8],  (const float*)d_in[9],  (const float*)d_in[10],
        (const float*)d_in[11], (const float*)d_in[12], (const float*)d_in[13],
        (const float*)d_in[14], (const float*)d_in[15], (const float*)d_in[16],
        (const float*)d_in[17], (const float*)d_in[18], (const float*)d_in[19]);

    proj_kernel<<<dim3(N_PIX / 256, 10, B_SZ), 128>>>(x1, x2);

    cudaFuncSetAttribute(flash_mma, cudaFuncAttributeMaxDynamicSharedMemorySize, SMEM_TOTAL);
    flash_mma<<<dim3(N_PIX / M_TILE, B_SZ), 512, SMEM_TOTAL>>>((float*)d_out);
}

// round 12
// speedup vs baseline: 12.0153x; 1.1851x over previous
#include <cuda_runtime.h>
#include <cuda_fp16.h>
#include <cstdint>

#define N_PIX  4096
#define C_IN   256
#define B_SZ   4
#define TN     128
#define NTILES (N_PIX / TN)     // 32
#define M_TILE 128

// smem byte offsets
#define SQ   0                          // [128 m][32 d] fp16 single, stride 80
#define SKB(st) (10240 + (st) * 10240)  // [128 n][32 d] fp16 single, stride 80
#define SV   30720                      // [128 n][256 c] fp16, stride 528
#define SP   98304                      // [128 m][128 k] fp16, stride 272
#define SLP  133120                     // 2 x 128 float partial row sums
#define SMEM_TOTAL 134144

#define QK_STR 80
#define P_STR  272
#define V_STR  528

// ---------------- device scratch ----------------
__device__ __align__(16) __half g_Qs[B_SZ * N_PIX * 32];            // [b][m][32 d], scale*log2e folded
__device__ __align__(16) __half g_Ks[B_SZ * N_PIX * 32];            // [b][n][32 d]
__device__ __align__(16) __half g_V[(size_t)B_SZ * N_PIX * C_IN];   // [b][n][c]
__device__ __align__(16) float g_Wf[320 * C_IN];
__device__ float g_Bf[320];

// ---------------- helpers ----------------
__device__ __forceinline__ uint32_t s2u(const void* p) {
    uint32_t a;
    asm("{ .reg .u64 t; cvta.to.shared.u64 t, %1; cvt.u32.u64 %0, t; }" : "=r"(a) : "l"(p));
    return a;
}
__device__ __forceinline__ void cp16(uint32_t dst, const void* src) {
    asm volatile("cp.async.cg.shared.global [%0], [%1], 16;\n" :: "r"(dst), "l"(src));
}
#define CP_COMMIT() asm volatile("cp.async.commit_group;\n" ::: "memory")
#define CP_WAITN(n) asm volatile("cp.async.wait_group %0;\n" :: "n"(n) : "memory")

__device__ __forceinline__ void ldsm4(uint32_t& r0, uint32_t& r1, uint32_t& r2, uint32_t& r3, uint32_t a) {
    asm volatile("ldmatrix.sync.aligned.m8n8.x4.shared.b16 {%0,%1,%2,%3}, [%4];"
                 : "=r"(r0), "=r"(r1), "=r"(r2), "=r"(r3) : "r"(a));
}
__device__ __forceinline__ void ldsm4t(uint32_t& r0, uint32_t& r1, uint32_t& r2, uint32_t& r3, uint32_t a) {
    asm volatile("ldmatrix.sync.aligned.m8n8.x4.trans.shared.b16 {%0,%1,%2,%3}, [%4];"
                 : "=r"(r0), "=r"(r1), "=r"(r2), "=r"(r3) : "r"(a));
}
__device__ __forceinline__ void stsm4(uint32_t a, uint32_t r0, uint32_t r1, uint32_t r2, uint32_t r3) {
    asm volatile("stmatrix.sync.aligned.m8n8.x4.shared.b16 [%0], {%1,%2,%3,%4};"
                 :: "r"(a), "r"(r0), "r"(r1), "r"(r2), "r"(r3) : "memory");
}
__device__ __forceinline__ void mma_f16(float* c, uint32_t a0, uint32_t a1, uint32_t a2, uint32_t a3,
                                        uint32_t b0, uint32_t b1) {
    asm volatile(
        "mma.sync.aligned.m16n8k16.row.col.f32.f16.f16.f32 "
        "{%0,%1,%2,%3}, {%4,%5,%6,%7}, {%8,%9}, {%0,%1,%2,%3};"
        : "+f"(c[0]), "+f"(c[1]), "+f"(c[2]), "+f"(c[3])
        : "r"(a0), "r"(a1), "r"(a2), "r"(a3), "r"(b0), "r"(b1));
}
__device__ __forceinline__ float ex2f(float x) {
    float e; asm("ex2.approx.ftz.f32 %0, %1;" : "=f"(e) : "f"(x)); return e;
}

__device__ __forceinline__ unsigned long long pack2(float x, float y) {
    unsigned long long r;
    asm("mov.b64 %0, {%1, %2};" : "=l"(r) : "f"(x), "f"(y));
    return r;
}
__device__ __forceinline__ unsigned long long dup2(float x) { return pack2(x, x); }
__device__ __forceinline__ unsigned long long ffma2(unsigned long long a, unsigned long long b,
                                                    unsigned long long c) {
    unsigned long long d;
    asm("fma.rn.f32x2 %0, %1, %2, %3;" : "=l"(d) : "l"(a), "l"(b), "l"(c));
    return d;
}
__device__ __forceinline__ void unpack2(unsigned long long v, float& x, float& y) {
    asm("mov.b64 {%0, %1}, %2;" : "=f"(x), "=f"(y) : "l"(v));
}

// ---------------- fold BN into 1x1-conv weights ----------------
__global__ void fold_kernel(
    const float* __restrict__ qw, const float* __restrict__ qb,
    const float* __restrict__ qg, const float* __restrict__ qbe,
    const float* __restrict__ qm, const float* __restrict__ qv,
    const float* __restrict__ kw, const float* __restrict__ kb,
    const float* __restrict__ kg, const float* __restrict__ kbe,
    const float* __restrict__ km, const float* __restrict__ kv,
    const float* __restrict__ vw, const float* __restrict__ vb,
    const float* __restrict__ vg, const float* __restrict__ vbe,
    const float* __restrict__ vm, const float* __restrict__ vv)
{
    int r = blockIdx.x;
    const float *w, *bb, *g, *be, *mn, *vr; int j;
    if (r < 32)      { w = qw; bb = qb; g = qg; be = qbe; mn = qm; vr = qv; j = r; }
    else if (r < 64) { w = kw; bb = kb; g = kg; be = kbe; mn = km; vr = kv; j = r - 32; }
    else             { w = vw; bb = vb; g = vg; be = vbe; mn = vm; vr = vv; j = r - 64; }
    float inv = g[j] * rsqrtf(vr[j] + 1e-5f);
    int c = threadIdx.x;
    g_Wf[r * C_IN + c] = w[j * C_IN + c] * inv;
    if (c == 0) g_Bf[r] = bb[j] * inv + be[j] - mn[j] * inv;
}

// ---------------- projection -> fp16 operands (2 pixels per thread) ----------------
// grid: (N_PIX/256, 10 segs, B). seg 0 -> Q(x1), 1 -> K(x2), 2-9 -> V(x2)
__global__ __launch_bounds__(128) void proj_kernel(
    const float* __restrict__ x1, const float* __restrict__ x2)
{
    __shared__ float2 sW2[C_IN * 16];
    int seg = blockIdx.y, b = blockIdx.z;
    int tid = threadIdx.x;
    int n = blockIdx.x * 256 + tid;        // pixel A; pixel B = n + 128
    int r0 = seg * 32;
    for (int i = tid; i < C_IN * 16; i += 128) {
        int c = i >> 4, dp = i & 15;
        sW2[i] = make_float2(g_Wf[(r0 + 2 * dp) * C_IN + c],
                             g_Wf[(r0 + 2 * dp + 1) * C_IN + c]);
    }
    __syncthreads();

    const float* x  = (seg == 0) ? x1 : x2;
    const float* xa = x + (size_t)b * C_IN * N_PIX + n;
    const float* xc = xa + 128;

    unsigned long long accA[16], accB[16];
#pragma unroll
    for (int dp = 0; dp < 16; ++dp) { accA[dp] = 0ull; accB[dp] = 0ull; }

#pragma unroll 2
    for (int c = 0; c < C_IN; c += 4) {
        float xva[4], xvb[4];
#pragma unroll
        for (int u = 0; u < 4; ++u) { xva[u] = xa[(c + u) * N_PIX]; xvb[u] = xc[(c + u) * N_PIX]; }
#pragma unroll
        for (int u = 0; u < 4; ++u) {
            unsigned long long xdA = dup2(xva[u]);
            unsigned long long xdB = dup2(xvb[u]);
            const ulonglong2* wr = (const ulonglong2*)&sW2[(c + u) * 16];
#pragma unroll
            for (int q = 0; q < 8; ++q) {
                ulonglong2 w = wr[q];
                accA[2 * q]     = ffma2(w.x, xdA, accA[2 * q]);
                accA[2 * q + 1] = ffma2(w.y, xdA, accA[2 * q + 1]);
                accB[2 * q]     = ffma2(w.x, xdB, accB[2 * q]);
                accB[2 * q + 1] = ffma2(w.y, xdB, accB[2 * q + 1]);
            }
        }
    }

#pragma unroll
    for (int px = 0; px < 2; ++px) {
        const unsigned long long* acc2 = (px == 0) ? accA : accB;
        int np = n + px * 128;
        float f[32];
#pragma unroll
        for (int dp = 0; dp < 16; ++dp) unpack2(acc2[dp], f[2 * dp], f[2 * dp + 1]);
#pragma unroll
        for (int d = 0; d < 32; ++d) f[d] += g_Bf[r0 + d];

        if (seg == 0) {
            const float qs = 0.17677669529663689f * 1.4426950408889634f;  // scale * log2(e)
#pragma unroll
            for (int d = 0; d < 32; ++d) f[d] *= qs;
        }

        uint32_t uh[16];
#pragma unroll
        for (int j = 0; j < 16; ++j) {
            __half2 h2 = __floats2half2_rn(f[2 * j], f[2 * j + 1]);
            uh[j] = *reinterpret_cast<uint32_t*>(&h2);
        }

        if (seg < 2) {
            char* dst = (char*)((seg == 0) ? g_Qs : g_Ks) + ((size_t)(b * N_PIX + np)) * 64;
#pragma unroll
            for (int q = 0; q < 4; ++q)
                *(uint4*)(dst + q * 16) = make_uint4(uh[4 * q], uh[4 * q + 1], uh[4 * q + 2], uh[4 * q + 3]);
        } else {
            int c0 = (seg - 2) * 32;
            char* dh = (char*)g_V + (((size_t)(b * N_PIX + np)) * C_IN + c0) * 2;
#pragma unroll
            for (int q = 0; q < 4; ++q)
                *(uint4*)(dh + q * 16) = make_uint4(uh[4 * q], uh[4 * q + 1], uh[4 * q + 2], uh[4 * q + 3]);
        }
    }
}

// ---------------- flash attention: fp16 mma.sync, single-term S, PV m32xc64 ----------------
// grid: (N_PIX/128, B), 512 threads = 16 warps, occ 1.
// S phase:  warp w -> m-slice (w&7)*16, n-half (w>>3)*64 (two n32 sub-passes)
// PV phase: warp w -> m-slice (w&3)*32 (two m16 tiles), c-quarter (w>>2)*64
__global__ __launch_bounds__(512, 1) void flash_mma(float* __restrict__ out)
{
    extern __shared__ __align__(16) char sm[];
    const uint32_t sb = s2u(sm);
    const int tid  = threadIdx.x;
    const int warp = tid >> 5;
    const int lane = tid & 31;
    const int ms   = (warp & 7) * 16;    // S-phase m slice
    const int half = warp >> 3;          // S-phase n half
    const int mw   = (warp & 3) * 32;    // PV m base (two m16 tiles)
    const int cq   = (warp >> 2) * 64;   // PV c quarter (elements)
    const int b    = blockIdx.y;
    const int m_base = blockIdx.x * M_TILE;

    const char* gkb = (const char*)g_Ks + ((size_t)b * N_PIX) * 64;
    const char* gvb = (const char*)g_V + ((size_t)b * N_PIX) * C_IN * 2;

    // ---- Q tile (persistent, plain stores) ----
    {
        const char* gq = (const char*)g_Qs + ((size_t)(b * N_PIX + m_base)) * 64;
        {
            int m = tid >> 2, q = tid & 3;
            uint4 v = *(const uint4*)(gq + (size_t)m * 64 + q * 16);
            *(uint4*)(sm + SQ + m * QK_STR + q * 16) = v;
        }
    }

    float O[2][8][4];
#pragma unroll
    for (int mt = 0; mt < 2; ++mt)
#pragma unroll
        for (int j = 0; j < 8; ++j)
#pragma unroll
            for (int k = 0; k < 4; ++k) O[mt][j][k] = 0.f;
    float rs0 = 0.f, rs1 = 0.f;

    auto load_k = [&](int t, int st) {
        const char* gk = gkb + (size_t)t * TN * 64;
        int n = tid >> 2, q = tid & 3;
        cp16(sb + SKB(st) + n * QK_STR + q * 16, gk + (size_t)n * 64 + q * 16);
    };
    auto load_v = [&](int t) {
        const char* gv = gvb + (size_t)t * TN * C_IN * 2;
        for (int i = tid; i < 4096; i += 512) {
            int n = i >> 5, q = i & 31;
            cp16(sb + SV + n * V_STR + q * 16, gv + (size_t)n * 512 + q * 16);
        }
    };

    // prologue: K(0), V(0)
    load_k(0, 0);
    CP_COMMIT();
    load_v(0);
    CP_COMMIT();

#pragma unroll 1
    for (int t = 0; t < NTILES; ++t) {
        const int st = t & 1;
        if (t + 1 < NTILES) {
            load_k(t + 1, st ^ 1);
            CP_COMMIT();
            CP_WAITN(2);   // K(t) done; V(t), K(t+1) in flight
        } else {
            CP_WAITN(1);   // K(t) done; V(t) in flight
        }
        __syncthreads();

        // ---- S = Q K^T (single-term fp16), two n32 sub-passes ----
#pragma unroll
        for (int np = 0; np < 2; ++np) {
            float acc[4][4];
#pragma unroll
            for (int j = 0; j < 4; ++j)
#pragma unroll
                for (int k = 0; k < 4; ++k) acc[j][k] = 0.f;

#pragma unroll
            for (int kt = 0; kt < 2; ++kt) {
                uint32_t a0, a1, a2, a3;
                ldsm4(a0, a1, a2, a3,
                      sb + SQ + (ms + (lane & 15)) * QK_STR + kt * 32 + (lane >> 4) * 16);
#pragma unroll
                for (int nb = 0; nb < 2; ++nb) {
                    int nbase = half * 64 + np * 32 + nb * 16;
                    uint32_t row = nbase + ((lane >> 4) << 3) + (lane & 7);
                    uint32_t col = kt * 32 + ((lane >> 3) & 1) * 16;
                    uint32_t b0, b1, b2, b3;
                    ldsm4(b0, b1, b2, b3, sb + SKB(st) + row * QK_STR + col);
                    mma_f16(acc[2 * nb],     a0, a1, a2, a3, b0, b1);
                    mma_f16(acc[2 * nb + 1], a0, a1, a2, a3, b2, b3);
                }
            }

            // P = exp2(S) unnormalized; row sums; pack fp16
            uint32_t p01h[4], p23h[4];
#pragma unroll
            for (int j = 0; j < 4; ++j) {
                float p0 = ex2f(acc[j][0]), p1 = ex2f(acc[j][1]);
                float p2 = ex2f(acc[j][2]), p3 = ex2f(acc[j][3]);
                rs0 += p0 + p1;
                rs1 += p2 + p3;
                __half2 h01 = __floats2half2_rn(p0, p1);
                __half2 h23 = __floats2half2_rn(p2, p3);
                p01h[j] = *reinterpret_cast<uint32_t*>(&h01);
                p23h[j] = *reinterpret_cast<uint32_t*>(&h23);
            }

            // stmatrix P: [128 m][128 k], warp writes m16 x k32 at col half*128 + np*64
            int g = lane >> 3;
            uint32_t row = ms + (g & 1) * 8 + (lane & 7);
            uint32_t colb = half * 128 + np * 64 + (g >> 1) * 16;
            uint32_t a0 = sb + SP + row * P_STR + colb;
            stsm4(a0,      p01h[0], p23h[0], p01h[1], p23h[1]);
            stsm4(a0 + 32, p01h[2], p23h[2], p01h[3], p23h[3]);
        }

        // ---- wait V(t), then PV: warp m32 x c64 ----
        if (t + 1 < NTILES) CP_WAITN(1);
        else                CP_WAITN(0);
        __syncthreads();

#pragma unroll
        for (int kt = 0; kt < 8; ++kt) {
            uint32_t p0a, p0b, p0c, p0d, p1a, p1b, p1c, p1d;
            ldsm4(p0a, p0b, p0c, p0d,
                  sb + SP + (mw + (lane & 15)) * P_STR + kt * 32 + (lane >> 4) * 16);
            ldsm4(p1a, p1b, p1c, p1d,
                  sb + SP + (mw + 16 + (lane & 15)) * P_STR + kt * 32 + (lane >> 4) * 16);
            uint32_t vrow = kt * 16 + ((lane >> 3) & 1) * 8 + (lane & 7);
#pragma unroll
            for (int vb = 0; vb < 4; ++vb) {
                uint32_t colb = cq * 2 + vb * 32 + ((lane >> 4) & 1) * 16;
                uint32_t b0, b1, b2, b3;
                ldsm4t(b0, b1, b2, b3, sb + SV + vrow * V_STR + colb);
                int j = vb * 2;
                mma_f16(O[0][j],     p0a, p0b, p0c, p0d, b0, b1);
                mma_f16(O[0][j + 1], p0a, p0b, p0c, p0d, b2, b3);
                mma_f16(O[1][j],     p1a, p1b, p1c, p1d, b0, b1);
                mma_f16(O[1][j + 1], p1a, p1b, p1c, p1d, b2, b3);
            }
        }
        __syncthreads();

        // ---- issue V(t+1) (overlaps next tile's S phase) ----
        if (t + 1 < NTILES) {
            load_v(t + 1);
            CP_COMMIT();
        }
    }

    // ---- epilogue: combine row sums, normalize, store ----
    rs0 += __shfl_xor_sync(0xffffffffu, rs0, 1);
    rs0 += __shfl_xor_sync(0xffffffffu, rs0, 2);
    rs1 += __shfl_xor_sync(0xffffffffu, rs1, 1);
    rs1 += __shfl_xor_sync(0xffffffffu, rs1, 2);
    float* sLp = (float*)(sm + SLP);
    if ((lane & 3) == 0) {
        sLp[half * 128 + ms + (lane >> 2)]     = rs0;
        sLp[half * 128 + ms + (lane >> 2) + 8] = rs1;
    }
    __syncthreads();

    float* ob = out + (size_t)b * C_IN * N_PIX + m_base;
#pragma unroll
    for (int mt = 0; mt < 2; ++mt) {
        int r0 = mw + mt * 16 + (lane >> 2);
        float inv0 = 1.0f / (sLp[r0] + sLp[128 + r0]);
        float inv1 = 1.0f / (sLp[r0 + 8] + sLp[128 + r0 + 8]);
#pragma unroll
        for (int j = 0; j < 8; ++j) {
            int c = cq + j * 8 + 2 * (lane & 3);
            ob[(size_t)c * N_PIX + r0]           = O[mt][j][0] * inv0;
            ob[(size_t)(c + 1) * N_PIX + r0]     = O[mt][j][1] * inv0;
            ob[(size_t)c * N_PIX + r0 + 8]       = O[mt][j][2] * inv1;
            ob[(size_t)(c + 1) * N_PIX + r0 + 8] = O[mt][j][3] * inv1;
        }
    }
}

// ---------------- launch ----------------
extern "C" void kernel_launch(void* const* d_in, const int* in_sizes, int n_in,
                              void* d_out, int out_size)
{
    const float* x1 = (const float*)d_in[0];
    const float* x2 = (const float*)d_in[1];

    fold_kernel<<<320, 256>>>(
        (const float*)d_in[2],  (const float*)d_in[3],  (const float*)d_in[4],
        (const float*)d_in[5],  (const float*)d_in[6],  (const float*)d_in[7],
        (const float*)d_in[8],  (const float*)d_in[9],  (const float*)d_in[10],
        (const float*)d_in[11], (const float*)d_in[12], (const float*)d_in[13],
        (const float*)d_in[14], (const float*)d_in[15], (const float*)d_in[16],
        (const float*)d_in[17], (const float*)d_in[18], (const float*)d_in[19]);

    proj_kernel<<<dim3(N_PIX / 256, 10, B_SZ), 128>>>(x1, x2);

    cudaFuncSetAttribute(flash_mma, cudaFuncAttributeMaxDynamicSharedMemorySize, SMEM_TOTAL);
    flash_mma<<<dim3(N_PIX / M_TILE, B_SZ), 512, SMEM_TOTAL>>>((float*)d_out);
}

// round 13
// speedup vs baseline: 12.1148x; 1.0083x over previous
#include <cuda_runtime.h>
#include <cuda_fp16.h>
#include <cstdint>

#define N_PIX  4096
#define C_IN   256
#define B_SZ   4
#define TN     128
#define NTILES (N_PIX / TN)     // 32
#define M_TILE 64

// smem byte offsets (M_TILE=64, occ-2 budget: 111104 B <= ~113 KB)
#define SQ   0                          // [64 m][32 d] fp16, stride 80  (5120)
#define SKB(st) (5120 + (st) * 10240)   // [128 n][32 d] fp16, stride 80 (2 stages)
#define SV   25600                      // [128 n][256 c] fp16, stride 528 (67584)
#define SP   93184                      // [64 m][128 k] fp16, stride 272 (17408)
#define SLP  110592                     // 2 x 64 float partial row sums (512)
#define SMEM_TOTAL 111104

#define QK_STR 80
#define P_STR  272
#define V_STR  528

// ---------------- device scratch ----------------
__device__ __align__(16) __half g_Qs[B_SZ * N_PIX * 32];            // [b][m][32 d], scale*log2e folded
__device__ __align__(16) __half g_Ks[B_SZ * N_PIX * 32];            // [b][n][32 d]
__device__ __align__(16) __half g_V[(size_t)B_SZ * N_PIX * C_IN];   // [b][n][c]
__device__ __align__(16) float g_Wf[320 * C_IN];
__device__ float g_Bf[320];

// ---------------- helpers ----------------
__device__ __forceinline__ uint32_t s2u(const void* p) {
    uint32_t a;
    asm("{ .reg .u64 t; cvta.to.shared.u64 t, %1; cvt.u32.u64 %0, t; }" : "=r"(a) : "l"(p));
    return a;
}
__device__ __forceinline__ void cp16(uint32_t dst, const void* src) {
    asm volatile("cp.async.cg.shared.global [%0], [%1], 16;\n" :: "r"(dst), "l"(src));
}
#define CP_COMMIT() asm volatile("cp.async.commit_group;\n" ::: "memory")
#define CP_WAITN(n) asm volatile("cp.async.wait_group %0;\n" :: "n"(n) : "memory")

__device__ __forceinline__ void ldsm4(uint32_t& r0, uint32_t& r1, uint32_t& r2, uint32_t& r3, uint32_t a) {
    asm volatile("ldmatrix.sync.aligned.m8n8.x4.shared.b16 {%0,%1,%2,%3}, [%4];"
                 : "=r"(r0), "=r"(r1), "=r"(r2), "=r"(r3) : "r"(a));
}
__device__ __forceinline__ void ldsm4t(uint32_t& r0, uint32_t& r1, uint32_t& r2, uint32_t& r3, uint32_t a) {
    asm volatile("ldmatrix.sync.aligned.m8n8.x4.trans.shared.b16 {%0,%1,%2,%3}, [%4];"
                 : "=r"(r0), "=r"(r1), "=r"(r2), "=r"(r3) : "r"(a));
}
__device__ __forceinline__ void stsm4(uint32_t a, uint32_t r0, uint32_t r1, uint32_t r2, uint32_t r3) {
    asm volatile("stmatrix.sync.aligned.m8n8.x4.shared.b16 [%0], {%1,%2,%3,%4};"
                 :: "r"(a), "r"(r0), "r"(r1), "r"(r2), "r"(r3) : "memory");
}
__device__ __forceinline__ void mma_f16(float* c, uint32_t a0, uint32_t a1, uint32_t a2, uint32_t a3,
                                        uint32_t b0, uint32_t b1) {
    asm volatile(
        "mma.sync.aligned.m16n8k16.row.col.f32.f16.f16.f32 "
        "{%0,%1,%2,%3}, {%4,%5,%6,%7}, {%8,%9}, {%0,%1,%2,%3};"
        : "+f"(c[0]), "+f"(c[1]), "+f"(c[2]), "+f"(c[3])
        : "r"(a0), "r"(a1), "r"(a2), "r"(a3), "r"(b0), "r"(b1));
}
__device__ __forceinline__ float ex2f(float x) {
    float e; asm("ex2.approx.ftz.f32 %0, %1;" : "=f"(e) : "f"(x)); return e;
}

__device__ __forceinline__ unsigned long long pack2(float x, float y) {
    unsigned long long r;
    asm("mov.b64 %0, {%1, %2};" : "=l"(r) : "f"(x), "f"(y));
    return r;
}
__device__ __forceinline__ unsigned long long dup2(float x) { return pack2(x, x); }
__device__ __forceinline__ unsigned long long ffma2(unsigned long long a, unsigned long long b,
                                                    unsigned long long c) {
    unsigned long long d;
    asm("fma.rn.f32x2 %0, %1, %2, %3;" : "=l"(d) : "l"(a), "l"(b), "l"(c));
    return d;
}
__device__ __forceinline__ void unpack2(unsigned long long v, float& x, float& y) {
    asm("mov.b64 {%0, %1}, %2;" : "=f"(x), "=f"(y) : "l"(v));
}

// ---------------- fold BN into 1x1-conv weights ----------------
__global__ void fold_kernel(
    const float* __restrict__ qw, const float* __restrict__ qb,
    const float* __restrict__ qg, const float* __restrict__ qbe,
    const float* __restrict__ qm, const float* __restrict__ qv,
    const float* __restrict__ kw, const float* __restrict__ kb,
    const float* __restrict__ kg, const float* __restrict__ kbe,
    const float* __restrict__ km, const float* __restrict__ kv,
    const float* __restrict__ vw, const float* __restrict__ vb,
    const float* __restrict__ vg, const float* __restrict__ vbe,
    const float* __restrict__ vm, const float* __restrict__ vv)
{
    int r = blockIdx.x;
    const float *w, *bb, *g, *be, *mn, *vr; int j;
    if (r < 32)      { w = qw; bb = qb; g = qg; be = qbe; mn = qm; vr = qv; j = r; }
    else if (r < 64) { w = kw; bb = kb; g = kg; be = kbe; mn = km; vr = kv; j = r - 32; }
    else             { w = vw; bb = vb; g = vg; be = vbe; mn = vm; vr = vv; j = r - 64; }
    float inv = g[j] * rsqrtf(vr[j] + 1e-5f);
    int c = threadIdx.x;
    g_Wf[r * C_IN + c] = w[j * C_IN + c] * inv;
    if (c == 0) g_Bf[r] = bb[j] * inv + be[j] - mn[j] * inv;
}

// ---------------- projection -> fp16 operands (2 pixels per thread) ----------------
// grid: (N_PIX/256, 10 segs, B). seg 0 -> Q(x1), 1 -> K(x2), 2-9 -> V(x2)
__global__ __launch_bounds__(128) void proj_kernel(
    const float* __restrict__ x1, const float* __restrict__ x2)
{
    __shared__ float2 sW2[C_IN * 16];
    int seg = blockIdx.y, b = blockIdx.z;
    int tid = threadIdx.x;
    int n = blockIdx.x * 256 + tid;        // pixel A; pixel B = n + 128
    int r0 = seg * 32;
    for (int i = tid; i < C_IN * 16; i += 128) {
        int c = i >> 4, dp = i & 15;
        sW2[i] = make_float2(g_Wf[(r0 + 2 * dp) * C_IN + c],
                             g_Wf[(r0 + 2 * dp + 1) * C_IN + c]);
    }
    __syncthreads();

    const float* x  = (seg == 0) ? x1 : x2;
    const float* xa = x + (size_t)b * C_IN * N_PIX + n;
    const float* xc = xa + 128;

    unsigned long long accA[16], accB[16];
#pragma unroll
    for (int dp = 0; dp < 16; ++dp) { accA[dp] = 0ull; accB[dp] = 0ull; }

#pragma unroll 2
    for (int c = 0; c < C_IN; c += 4) {
        float xva[4], xvb[4];
#pragma unroll
        for (int u = 0; u < 4; ++u) { xva[u] = xa[(c + u) * N_PIX]; xvb[u] = xc[(c + u) * N_PIX]; }
#pragma unroll
        for (int u = 0; u < 4; ++u) {
            unsigned long long xdA = dup2(xva[u]);
            unsigned long long xdB = dup2(xvb[u]);
            const ulonglong2* wr = (const ulonglong2*)&sW2[(c + u) * 16];
#pragma unroll
            for (int q = 0; q < 8; ++q) {
                ulonglong2 w = wr[q];
                accA[2 * q]     = ffma2(w.x, xdA, accA[2 * q]);
                accA[2 * q + 1] = ffma2(w.y, xdA, accA[2 * q + 1]);
                accB[2 * q]     = ffma2(w.x, xdB, accB[2 * q]);
                accB[2 * q + 1] = ffma2(w.y, xdB, accB[2 * q + 1]);
            }
        }
    }

#pragma unroll
    for (int px = 0; px < 2; ++px) {
        const unsigned long long* acc2 = (px == 0) ? accA : accB;
        int np = n + px * 128;
        float f[32];
#pragma unroll
        for (int dp = 0; dp < 16; ++dp) unpack2(acc2[dp], f[2 * dp], f[2 * dp + 1]);
#pragma unroll
        for (int d = 0; d < 32; ++d) f[d] += g_Bf[r0 + d];

        if (seg == 0) {
            const float qs = 0.17677669529663689f * 1.4426950408889634f;  // scale * log2(e)
#pragma unroll
            for (int d = 0; d < 32; ++d) f[d] *= qs;
        }

        uint32_t uh[16];
#pragma unroll
        for (int j = 0; j < 16; ++j) {
            __half2 h2 = __floats2half2_rn(f[2 * j], f[2 * j + 1]);
            uh[j] = *reinterpret_cast<uint32_t*>(&h2);
        }

        if (seg < 2) {
            char* dst = (char*)((seg == 0) ? g_Qs : g_Ks) + ((size_t)(b * N_PIX + np)) * 64;
#pragma unroll
            for (int q = 0; q < 4; ++q)
                *(uint4*)(dst + q * 16) = make_uint4(uh[4 * q], uh[4 * q + 1], uh[4 * q + 2], uh[4 * q + 3]);
        } else {
            int c0 = (seg - 2) * 32;
            char* dh = (char*)g_V + (((size_t)(b * N_PIX + np)) * C_IN + c0) * 2;
#pragma unroll
            for (int q = 0; q < 4; ++q)
                *(uint4*)(dh + q * 16) = make_uint4(uh[4 * q], uh[4 * q + 1], uh[4 * q + 2], uh[4 * q + 3]);
        }
    }
}

// ---------------- flash attention: fp16 mma.sync, M_TILE=64, occ 2 ----------------
// grid: (N_PIX/64, B), 256 threads = 8 warps, 2 CTAs/SM.
// S phase:  warp w -> m-slice (w&3)*16, n-half (w>>2)*64 (two n32 sub-passes)
// PV phase: warp w -> m-slice (w&1)*32 (two m16 tiles), c-quarter (w>>1)*64
__global__ __launch_bounds__(256, 2) void flash_mma(float* __restrict__ out)
{
    extern __shared__ __align__(16) char sm[];
    const uint32_t sb = s2u(sm);
    const int tid  = threadIdx.x;
    const int warp = tid >> 5;
    const int lane = tid & 31;
    const int ms   = (warp & 3) * 16;    // S-phase m slice
    const int half = warp >> 2;          // S-phase n half
    const int mw   = (warp & 1) * 32;    // PV m base (two m16 tiles)
    const int cq   = (warp >> 1) * 64;   // PV c quarter (elements)
    const int b    = blockIdx.y;
    const int m_base = blockIdx.x * M_TILE;

    const char* gkb = (const char*)g_Ks + ((size_t)b * N_PIX) * 64;
    const char* gvb = (const char*)g_V + ((size_t)b * N_PIX) * C_IN * 2;

    // ---- Q tile (persistent, plain stores): 64 rows x 4 chunks = 256 threads ----
    {
        const char* gq = (const char*)g_Qs + ((size_t)(b * N_PIX + m_base)) * 64;
        int m = tid >> 2, q = tid & 3;
        uint4 v = *(const uint4*)(gq + (size_t)m * 64 + q * 16);
        *(uint4*)(sm + SQ + m * QK_STR + q * 16) = v;
    }

    float O[2][8][4];
#pragma unroll
    for (int mt = 0; mt < 2; ++mt)
#pragma unroll
        for (int j = 0; j < 8; ++j)
#pragma unroll
            for (int k = 0; k < 4; ++k) O[mt][j][k] = 0.f;
    float rs0 = 0.f, rs1 = 0.f;

    auto load_k = [&](int t, int st) {
        const char* gk = gkb + (size_t)t * TN * 64;
        for (int i = tid; i < 512; i += 256) {
            int n = i >> 2, q = i & 3;
            cp16(sb + SKB(st) + n * QK_STR + q * 16, gk + (size_t)n * 64 + q * 16);
        }
    };
    auto load_v = [&](int t) {
        const char* gv = gvb + (size_t)t * TN * C_IN * 2;
        for (int i = tid; i < 4096; i += 256) {
            int n = i >> 5, q = i & 31;
            cp16(sb + SV + n * V_STR + q * 16, gv + (size_t)n * 512 + q * 16);
        }
    };

    // prologue: K(0), V(0)
    load_k(0, 0);
    CP_COMMIT();
    load_v(0);
    CP_COMMIT();

#pragma unroll 1
    for (int t = 0; t < NTILES; ++t) {
        const int st = t & 1;
        if (t + 1 < NTILES) {
            load_k(t + 1, st ^ 1);
            CP_COMMIT();
            CP_WAITN(2);   // K(t) done; V(t), K(t+1) in flight
        } else {
            CP_WAITN(1);   // K(t) done; V(t) in flight
        }
        __syncthreads();

        // ---- S = Q K^T (single-term fp16), two n32 sub-passes ----
#pragma unroll
        for (int np = 0; np < 2; ++np) {
            float acc[4][4];
#pragma unroll
            for (int j = 0; j < 4; ++j)
#pragma unroll
                for (int k = 0; k < 4; ++k) acc[j][k] = 0.f;

#pragma unroll
            for (int kt = 0; kt < 2; ++kt) {
                uint32_t a0, a1, a2, a3;
                ldsm4(a0, a1, a2, a3,
                      sb + SQ + (ms + (lane & 15)) * QK_STR + kt * 32 + (lane >> 4) * 16);
#pragma unroll
                for (int nb = 0; nb < 2; ++nb) {
                    int nbase = half * 64 + np * 32 + nb * 16;
                    uint32_t row = nbase + ((lane >> 4) << 3) + (lane & 7);
                    uint32_t col = kt * 32 + ((lane >> 3) & 1) * 16;
                    uint32_t b0, b1, b2, b3;
                    ldsm4(b0, b1, b2, b3, sb + SKB(st) + row * QK_STR + col);
                    mma_f16(acc[2 * nb],     a0, a1, a2, a3, b0, b1);
                    mma_f16(acc[2 * nb + 1], a0, a1, a2, a3, b2, b3);
                }
            }

            // P = exp2(S) unnormalized; row sums; pack fp16
            uint32_t p01h[4], p23h[4];
#pragma unroll
            for (int j = 0; j < 4; ++j) {
                float p0 = ex2f(acc[j][0]), p1 = ex2f(acc[j][1]);
                float p2 = ex2f(acc[j][2]), p3 = ex2f(acc[j][3]);
                rs0 += p0 + p1;
                rs1 += p2 + p3;
                __half2 h01 = __floats2half2_rn(p0, p1);
                __half2 h23 = __floats2half2_rn(p2, p3);
                p01h[j] = *reinterpret_cast<uint32_t*>(&h01);
                p23h[j] = *reinterpret_cast<uint32_t*>(&h23);
            }

            // stmatrix P: [64 m][128 k], warp writes m16 x k32 at col half*128 + np*64
            int g = lane >> 3;
            uint32_t row = ms + (g & 1) * 8 + (lane & 7);
            uint32_t colb = half * 128 + np * 64 + (g >> 1) * 16;
            uint32_t a0 = sb + SP + row * P_STR + colb;
            stsm4(a0,      p01h[0], p23h[0], p01h[1], p23h[1]);
            stsm4(a0 + 32, p01h[2], p23h[2], p01h[3], p23h[3]);
        }

        // ---- wait V(t), then PV: warp m32 x c64 ----
        if (t + 1 < NTILES) CP_WAITN(1);
        else                CP_WAITN(0);
        __syncthreads();

#pragma unroll
        for (int kt = 0; kt < 8; ++kt) {
            uint32_t p0a, p0b, p0c, p0d, p1a, p1b, p1c, p1d;
            ldsm4(p0a, p0b, p0c, p0d,
                  sb + SP + (mw + (lane & 15)) * P_STR + kt * 32 + (lane >> 4) * 16);
            ldsm4(p1a, p1b, p1c, p1d,
                  sb + SP + (mw + 16 + (lane & 15)) * P_STR + kt * 32 + (lane >> 4) * 16);
            uint32_t vrow = kt * 16 + ((lane >> 3) & 1) * 8 + (lane & 7);
#pragma unroll
            for (int vb = 0; vb < 4; ++vb) {
                uint32_t colb = cq * 2 + vb * 32 + ((lane >> 4) & 1) * 16;
                uint32_t b0, b1, b2, b3;
                ldsm4t(b0, b1, b2, b3, sb + SV + vrow * V_STR + colb);
                int j = vb * 2;
                mma_f16(O[0][j],     p0a, p0b, p0c, p0d, b0, b1);
                mma_f16(O[0][j + 1], p0a, p0b, p0c, p0d, b2, b3);
                mma_f16(O[1][j],     p1a, p1b, p1c, p1d, b0, b1);
                mma_f16(O[1][j + 1], p1a, p1b, p1c, p1d, b2, b3);
            }
        }
        __syncthreads();

        // ---- issue V(t+1) (overlaps next tile's S phase) ----
        if (t + 1 < NTILES) {
            load_v(t + 1);
            CP_COMMIT();
        }
    }

    // ---- epilogue: combine row sums, normalize, store ----
    rs0 += __shfl_xor_sync(0xffffffffu, rs0, 1);
    rs0 += __shfl_xor_sync(0xffffffffu, rs0, 2);
    rs1 += __shfl_xor_sync(0xffffffffu, rs1, 1);
    rs1 += __shfl_xor_sync(0xffffffffu, rs1, 2);
    float* sLp = (float*)(sm + SLP);
    if ((lane & 3) == 0) {
        sLp[half * 64 + ms + (lane >> 2)]     = rs0;
        sLp[half * 64 + ms + (lane >> 2) + 8] = rs1;
    }
    __syncthreads();

    float* ob = out + (size_t)b * C_IN * N_PIX + m_base;
#pragma unroll
    for (int mt = 0; mt < 2; ++mt) {
        int r0 = mw + mt * 16 + (lane >> 2);
        float inv0 = 1.0f / (sLp[r0] + sLp[64 + r0]);
        float inv1 = 1.0f / (sLp[r0 + 8] + sLp[64 + r0 + 8]);
#pragma unroll
        for (int j = 0; j < 8; ++j) {
            int c = cq + j * 8 + 2 * (lane & 3);
            ob[(size_t)c * N_PIX + r0]           = O[mt][j][0] * inv0;
            ob[(size_t)(c + 1) * N_PIX + r0]     = O[mt][j][1] * inv0;
            ob[(size_t)c * N_PIX + r0 + 8]       = O[mt][j][2] * inv1;
            ob[(size_t)(c + 1) * N_PIX + r0 + 8] = O[mt][j][3] * inv1;
        }
    }
}

// ---------------- launch ----------------
extern "C" void kernel_launch(void* const* d_in, const int* in_sizes, int n_in,
                              void* d_out, int out_size)
{
    const float* x1 = (const float*)d_in[0];
    const float* x2 = (const float*)d_in[1];

    fold_kernel<<<320, 256>>>(
        (const float*)d_in[2],  (const float*)d_in[3],  (const float*)d_in[4],
        (const float*)d_in[5],  (const float*)d_in[6],  (const float*)d_in[7],
        (const float*)d_in[8],  (const float*)d_in[9],  (const float*)d_in[10],
        (const float*)d_in[11], (const float*)d_in[12], (const float*)d_in[13],
        (const float*)d_in[14], (const float*)d_in[15], (const float*)d_in[16],
        (const float*)d_in[17], (const float*)d_in[18], (const float*)d_in[19]);

    proj_kernel<<<dim3(N_PIX / 256, 10, B_SZ), 128>>>(x1, x2);

    cudaFuncSetAttribute(flash_mma, cudaFuncAttributeMaxDynamicSharedMemorySize, SMEM_TOTAL);
    flash_mma<<<dim3(N_PIX / M_TILE, B_SZ), 256, SMEM_TOTAL>>>((float*)d_out);
}

// round 14
// speedup vs baseline: 15.3895x; 1.2703x over previous
#include <cuda_runtime.h>
#include <cuda_fp16.h>
#include <cstdint>

#define N_PIX  4096
#define C_IN   256
#define B_SZ   4
#define TN     128
#define NTILES (N_PIX / TN)     // 32
#define M_TILE 64

// ---- flash smem byte offsets (M_TILE=64, occ-2) ----
#define SQ   0                          // [64 m][32 d] fp16, stride 80  (5120)
#define SKB(st) (5120 + (st) * 10240)   // [128 n][32 d] fp16, stride 80 (2 stages)
#define SV   25600                      // [128 n][256 c] fp16, stride 528 (67584)
#define SP   93184                      // [64 m][128 k] fp16, stride 272 (17408)
#define SLP  110592                     // 2 x 64 float partial row sums (512)
#define SMEM_TOTAL 111104

#define QK_STR 80
#define P_STR  272
#define V_STR  528

// ---- proj2 smem layout ----
#define PW_STR 528
#define PX_STR 528
#define PSW    0                        // W fp16 [32 m][256 k] stride 528 -> 16896
#define PSX(st) (16896 + (st) * 16896)  // X chunk fp16 [32 k][256 n] stride 528, 2 stages
#define PSMEM  50688

// ---------------- device scratch ----------------
__device__ __align__(16) __half g_Qs[B_SZ * N_PIX * 32];            // [b][m][32 d], scale*log2e folded
__device__ __align__(16) __half g_Ks[B_SZ * N_PIX * 32];            // [b][n][32 d]
__device__ __align__(16) __half g_V[(size_t)B_SZ * N_PIX * C_IN];   // [b][n][c]
__device__ __align__(16) float g_Wf[320 * C_IN];
__device__ float g_Bf[320];

// ---------------- helpers ----------------
__device__ __forceinline__ uint32_t s2u(const void* p) {
    uint32_t a;
    asm("{ .reg .u64 t; cvta.to.shared.u64 t, %1; cvt.u32.u64 %0, t; }" : "=r"(a) : "l"(p));
    return a;
}
__device__ __forceinline__ void cp16(uint32_t dst, const void* src) {
    asm volatile("cp.async.cg.shared.global [%0], [%1], 16;\n" :: "r"(dst), "l"(src));
}
#define CP_COMMIT() asm volatile("cp.async.commit_group;\n" ::: "memory")
#define CP_WAITN(n) asm volatile("cp.async.wait_group %0;\n" :: "n"(n) : "memory")

__device__ __forceinline__ void ldsm4(uint32_t& r0, uint32_t& r1, uint32_t& r2, uint32_t& r3, uint32_t a) {
    asm volatile("ldmatrix.sync.aligned.m8n8.x4.shared.b16 {%0,%1,%2,%3}, [%4];"
                 : "=r"(r0), "=r"(r1), "=r"(r2), "=r"(r3) : "r"(a));
}
__device__ __forceinline__ void ldsm4t(uint32_t& r0, uint32_t& r1, uint32_t& r2, uint32_t& r3, uint32_t a) {
    asm volatile("ldmatrix.sync.aligned.m8n8.x4.trans.shared.b16 {%0,%1,%2,%3}, [%4];"
                 : "=r"(r0), "=r"(r1), "=r"(r2), "=r"(r3) : "r"(a));
}
__device__ __forceinline__ void stsm4(uint32_t a, uint32_t r0, uint32_t r1, uint32_t r2, uint32_t r3) {
    asm volatile("stmatrix.sync.aligned.m8n8.x4.shared.b16 [%0], {%1,%2,%3,%4};"
                 :: "r"(a), "r"(r0), "r"(r1), "r"(r2), "r"(r3) : "memory");
}
__device__ __forceinline__ void mma_f16(float* c, uint32_t a0, uint32_t a1, uint32_t a2, uint32_t a3,
                                        uint32_t b0, uint32_t b1) {
    asm volatile(
        "mma.sync.aligned.m16n8k16.row.col.f32.f16.f16.f32 "
        "{%0,%1,%2,%3}, {%4,%5,%6,%7}, {%8,%9}, {%0,%1,%2,%3};"
        : "+f"(c[0]), "+f"(c[1]), "+f"(c[2]), "+f"(c[3])
        : "r"(a0), "r"(a1), "r"(a2), "r"(a3), "r"(b0), "r"(b1));
}
__device__ __forceinline__ float ex2f(float x) {
    float e; asm("ex2.approx.ftz.f32 %0, %1;" : "=f"(e) : "f"(x)); return e;
}

// ---------------- fold BN into 1x1-conv weights ----------------
__global__ void fold_kernel(
    const float* __restrict__ qw, const float* __restrict__ qb,
    const float* __restrict__ qg, const float* __restrict__ qbe,
    const float* __restrict__ qm, const float* __restrict__ qv,
    const float* __restrict__ kw, const float* __restrict__ kb,
    const float* __restrict__ kg, const float* __restrict__ kbe,
    const float* __restrict__ km, const float* __restrict__ kv,
    const float* __restrict__ vw, const float* __restrict__ vb,
    const float* __restrict__ vg, const float* __restrict__ vbe,
    const float* __restrict__ vm, const float* __restrict__ vv)
{
    int r = blockIdx.x;
    const float *w, *bb, *g, *be, *mn, *vr; int j;
    if (r < 32)      { w = qw; bb = qb; g = qg; be = qbe; mn = qm; vr = qv; j = r; }
    else if (r < 64) { w = kw; bb = kb; g = kg; be = kbe; mn = km; vr = kv; j = r - 32; }
    else             { w = vw; bb = vb; g = vg; be = vbe; mn = vm; vr = vv; j = r - 64; }
    float inv = g[j] * rsqrtf(vr[j] + 1e-5f);
    int c = threadIdx.x;
    g_Wf[r * C_IN + c] = w[j * C_IN + c] * inv;
    if (c == 0) g_Bf[r] = bb[j] * inv + be[j] - mn[j] * inv;
}

// ---------------- projection via tensor cores ----------------
// grid: (N_PIX/256, 10 segs, B), 256 threads = 8 warps.
// Y[32, 256px] = W[32,256] @ X[256, 256px] + bias; fp16 single precision operands.
// Warp w covers n-slice w*32 px, full m=32 (2 m16 tiles). k chunked by 32 (8 chunks).
__global__ __launch_bounds__(256) void proj2_kernel(
    const float* __restrict__ x1, const float* __restrict__ x2)
{
    __shared__ __align__(16) char sm[PSMEM];
    const uint32_t sb = s2u(sm);
    const int seg = blockIdx.y, b = blockIdx.z;
    const int tid = threadIdx.x;
    const int warp = tid >> 5, lane = tid & 31;
    const int nw = warp * 32;            // warp pixel base (within 256-px tile)
    const int px0 = blockIdx.x * 256;
    const int r0 = seg * 32;
    const float qs = (seg == 0) ? (0.17677669529663689f * 1.4426950408889634f) : 1.0f;

    // ---- W -> fp16 smem [32 m][256 k], stride 528 ----
    for (int i = tid; i < 2048; i += 256) {          // 2048 float4 = 32x256 floats
        int m = i >> 6, k4 = i & 63;
        float4 w = *(const float4*)&g_Wf[(r0 + m) * C_IN + k4 * 4];
        __half2 h0 = __floats2half2_rn(w.x * qs, w.y * qs);
        __half2 h1 = __floats2half2_rn(w.z * qs, w.w * qs);
        *(uint2*)(sm + PSW + m * PW_STR + k4 * 8) =
            make_uint2(*reinterpret_cast<uint32_t*>(&h0), *reinterpret_cast<uint32_t*>(&h1));
    }

    const float* xb = ((seg == 0) ? x1 : x2) + (size_t)b * C_IN * N_PIX + px0;

    // X chunk convert: [32 k][256 n] fp16 from fp32 global rows
    auto cvt_store = [&](const float4* f, int st) {
#pragma unroll
        for (int u = 0; u < 8; ++u) {
            int i = tid + u * 256;
            int c = i >> 6, n4 = i & 63;
            __half2 h0 = __floats2half2_rn(f[u].x, f[u].y);
            __half2 h1 = __floats2half2_rn(f[u].z, f[u].w);
            *(uint2*)(sm + PSX(st) + c * PX_STR + n4 * 8) =
                make_uint2(*reinterpret_cast<uint32_t*>(&h0), *reinterpret_cast<uint32_t*>(&h1));
        }
    };
    auto load_x = [&](int ch, float4* f) {
        const float* xs = xb + (size_t)(ch * 32) * N_PIX;
#pragma unroll
        for (int u = 0; u < 8; ++u) {
            int i = tid + u * 256;
            int c = i >> 6, n4 = i & 63;
            f[u] = *(const float4*)&xs[(size_t)c * N_PIX + n4 * 4];
        }
    };

    float O[2][4][4];
#pragma unroll
    for (int mt = 0; mt < 2; ++mt)
#pragma unroll
        for (int j = 0; j < 4; ++j)
#pragma unroll
            for (int k = 0; k < 4; ++k) O[mt][j][k] = 0.f;

    {
        float4 f[8];
        load_x(0, f);
        cvt_store(f, 0);
    }
    __syncthreads();

#pragma unroll 1
    for (int ch = 0; ch < 8; ++ch) {
        const int st = ch & 1;
        float4 f[8];
        if (ch < 7) load_x(ch + 1, f);   // LDG in flight during mma

#pragma unroll
        for (int kt = 0; kt < 2; ++kt) {
            uint32_t a0[4], a1[4];
            ldsm4(a0[0], a0[1], a0[2], a0[3],
                  sb + PSW + ((lane & 15)) * PW_STR + ch * 64 + kt * 32 + (lane >> 4) * 16);
            ldsm4(a1[0], a1[1], a1[2], a1[3],
                  sb + PSW + (16 + (lane & 15)) * PW_STR + ch * 64 + kt * 32 + (lane >> 4) * 16);
            uint32_t xrow = kt * 16 + ((lane >> 3) & 1) * 8 + (lane & 7);
#pragma unroll
            for (int nb = 0; nb < 2; ++nb) {
                uint32_t colb = nw * 2 + nb * 32 + ((lane >> 4) & 1) * 16;
                uint32_t b0, b1, b2, b3;
                ldsm4t(b0, b1, b2, b3, sb + PSX(st) + xrow * PX_STR + colb);
                int j = nb * 2;
                mma_f16(O[0][j],     a0[0], a0[1], a0[2], a0[3], b0, b1);
                mma_f16(O[0][j + 1], a0[0], a0[1], a0[2], a0[3], b2, b3);
                mma_f16(O[1][j],     a1[0], a1[1], a1[2], a1[3], b0, b1);
                mma_f16(O[1][j + 1], a1[0], a1[1], a1[2], a1[3], b2, b3);
            }
        }

        if (ch < 7) cvt_store(f, st ^ 1);
        __syncthreads();
    }

    // ---- epilogue: bias, pack, stsm to staging [32 m][256 n] (stage 0 region) ----
    {
        int g = lane >> 3;
#pragma unroll
        for (int mt = 0; mt < 2; ++mt) {
            float bias0 = g_Bf[r0 + mt * 16 + (lane >> 2)] * qs;
            float bias1 = g_Bf[r0 + mt * 16 + (lane >> 2) + 8] * qs;
            uint32_t p01[4], p23[4];
#pragma unroll
            for (int j = 0; j < 4; ++j) {
                __half2 h01 = __floats2half2_rn(O[mt][j][0] + bias0, O[mt][j][1] + bias0);
                __half2 h23 = __floats2half2_rn(O[mt][j][2] + bias1, O[mt][j][3] + bias1);
                p01[j] = *reinterpret_cast<uint32_t*>(&h01);
                p23[j] = *reinterpret_cast<uint32_t*>(&h23);
            }
            uint32_t row = mt * 16 + (g & 1) * 8 + (lane & 7);
            uint32_t colb = nw * 2 + (g >> 1) * 16;
            uint32_t a0 = sb + PSX(0) + row * PX_STR + colb;
            stsm4(a0,      p01[0], p23[0], p01[1], p23[1]);
            stsm4(a0 + 32, p01[2], p23[2], p01[3], p23[3]);
        }
    }
    __syncthreads();

    // ---- transpose out: thread = pixel, gather its 32 halves, coalesced 64B STG ----
    {
        uint32_t h[16];
#pragma unroll
        for (int j = 0; j < 16; ++j) {
            uint16_t lo, hi;
            asm volatile("ld.shared.u16 %0, [%1];" : "=h"(lo)
                         : "r"(sb + PSX(0) + (2 * j) * PX_STR + tid * 2));
            asm volatile("ld.shared.u16 %0, [%1];" : "=h"(hi)
                         : "r"(sb + PSX(0) + (2 * j + 1) * PX_STR + tid * 2));
            h[j] = (uint32_t)lo | ((uint32_t)hi << 16);
        }
        char* dst;
        if (seg < 2)
            dst = (char*)((seg == 0) ? g_Qs : g_Ks) + ((size_t)(b * N_PIX + px0 + tid)) * 64;
        else
            dst = (char*)g_V + (((size_t)(b * N_PIX + px0 + tid)) * C_IN + (seg - 2) * 32) * 2;
#pragma unroll
        for (int q = 0; q < 4; ++q)
            *(uint4*)(dst + q * 16) = make_uint4(h[4 * q], h[4 * q + 1], h[4 * q + 2], h[4 * q + 3]);
    }
}

// ---------------- flash attention: fp16 mma.sync, M_TILE=64, occ 2 (unchanged R13) ----------------
__global__ __launch_bounds__(256, 2) void flash_mma(float* __restrict__ out)
{
    extern __shared__ __align__(16) char sm[];
    const uint32_t sb = s2u(sm);
    const int tid  = threadIdx.x;
    const int warp = tid >> 5;
    const int lane = tid & 31;
    const int ms   = (warp & 3) * 16;
    const int half = warp >> 2;
    const int mw   = (warp & 1) * 32;
    const int cq   = (warp >> 1) * 64;
    const int b    = blockIdx.y;
    const int m_base = blockIdx.x * M_TILE;

    const char* gkb = (const char*)g_Ks + ((size_t)b * N_PIX) * 64;
    const char* gvb = (const char*)g_V + ((size_t)b * N_PIX) * C_IN * 2;

    {
        const char* gq = (const char*)g_Qs + ((size_t)(b * N_PIX + m_base)) * 64;
        int m = tid >> 2, q = tid & 3;
        uint4 v = *(const uint4*)(gq + (size_t)m * 64 + q * 16);
        *(uint4*)(sm + SQ + m * QK_STR + q * 16) = v;
    }

    float O[2][8][4];
#pragma unroll
    for (int mt = 0; mt < 2; ++mt)
#pragma unroll
        for (int j = 0; j < 8; ++j)
#pragma unroll
            for (int k = 0; k < 4; ++k) O[mt][j][k] = 0.f;
    float rs0 = 0.f, rs1 = 0.f;

    auto load_k = [&](int t, int st) {
        const char* gk = gkb + (size_t)t * TN * 64;
        for (int i = tid; i < 512; i += 256) {
            int n = i >> 2, q = i & 3;
            cp16(sb + SKB(st) + n * QK_STR + q * 16, gk + (size_t)n * 64 + q * 16);
        }
    };
    auto load_v = [&](int t) {
        const char* gv = gvb + (size_t)t * TN * C_IN * 2;
        for (int i = tid; i < 4096; i += 256) {
            int n = i >> 5, q = i & 31;
            cp16(sb + SV + n * V_STR + q * 16, gv + (size_t)n * 512 + q * 16);
        }
    };

    load_k(0, 0);
    CP_COMMIT();
    load_v(0);
    CP_COMMIT();

#pragma unroll 1
    for (int t = 0; t < NTILES; ++t) {
        const int st = t & 1;
        if (t + 1 < NTILES) {
            load_k(t + 1, st ^ 1);
            CP_COMMIT();
            CP_WAITN(2);
        } else {
            CP_WAITN(1);
        }
        __syncthreads();

#pragma unroll
        for (int np = 0; np < 2; ++np) {
            float acc[4][4];
#pragma unroll
            for (int j = 0; j < 4; ++j)
#pragma unroll
                for (int k = 0; k < 4; ++k) acc[j][k] = 0.f;

#pragma unroll
            for (int kt = 0; kt < 2; ++kt) {
                uint32_t a0, a1, a2, a3;
                ldsm4(a0, a1, a2, a3,
                      sb + SQ + (ms + (lane & 15)) * QK_STR + kt * 32 + (lane >> 4) * 16);
#pragma unroll
                for (int nb = 0; nb < 2; ++nb) {
                    int nbase = half * 64 + np * 32 + nb * 16;
                    uint32_t row = nbase + ((lane >> 4) << 3) + (lane & 7);
                    uint32_t col = kt * 32 + ((lane >> 3) & 1) * 16;
                    uint32_t b0, b1, b2, b3;
                    ldsm4(b0, b1, b2, b3, sb + SKB(st) + row * QK_STR + col);
                    mma_f16(acc[2 * nb],     a0, a1, a2, a3, b0, b1);
                    mma_f16(acc[2 * nb + 1], a0, a1, a2, a3, b2, b3);
                }
            }

            uint32_t p01h[4], p23h[4];
#pragma unroll
            for (int j = 0; j < 4; ++j) {
                float p0 = ex2f(acc[j][0]), p1 = ex2f(acc[j][1]);
                float p2 = ex2f(acc[j][2]), p3 = ex2f(acc[j][3]);
                rs0 += p0 + p1;
                rs1 += p2 + p3;
                __half2 h01 = __floats2half2_rn(p0, p1);
                __half2 h23 = __floats2half2_rn(p2, p3);
                p01h[j] = *reinterpret_cast<uint32_t*>(&h01);
                p23h[j] = *reinterpret_cast<uint32_t*>(&h23);
            }

            int g = lane >> 3;
            uint32_t row = ms + (g & 1) * 8 + (lane & 7);
            uint32_t colb = half * 128 + np * 64 + (g >> 1) * 16;
            uint32_t a0 = sb + SP + row * P_STR + colb;
            stsm4(a0,      p01h[0], p23h[0], p01h[1], p23h[1]);
            stsm4(a0 + 32, p01h[2], p23h[2], p01h[3], p23h[3]);
        }

        if (t + 1 < NTILES) CP_WAITN(1);
        else                CP_WAITN(0);
        __syncthreads();

#pragma unroll
        for (int kt = 0; kt < 8; ++kt) {
            uint32_t p0a, p0b, p0c, p0d, p1a, p1b, p1c, p1d;
            ldsm4(p0a, p0b, p0c, p0d,
                  sb + SP + (mw + (lane & 15)) * P_STR + kt * 32 + (lane >> 4) * 16);
            ldsm4(p1a, p1b, p1c, p1d,
                  sb + SP + (mw + 16 + (lane & 15)) * P_STR + kt * 32 + (lane >> 4) * 16);
            uint32_t vrow = kt * 16 + ((lane >> 3) & 1) * 8 + (lane & 7);
#pragma unroll
            for (int vb = 0; vb < 4; ++vb) {
                uint32_t colb = cq * 2 + vb * 32 + ((lane >> 4) & 1) * 16;
                uint32_t b0, b1, b2, b3;
                ldsm4t(b0, b1, b2, b3, sb + SV + vrow * V_STR + colb);
                int j = vb * 2;
                mma_f16(O[0][j],     p0a, p0b, p0c, p0d, b0, b1);
                mma_f16(O[0][j + 1], p0a, p0b, p0c, p0d, b2, b3);
                mma_f16(O[1][j],     p1a, p1b, p1c, p1d, b0, b1);
                mma_f16(O[1][j + 1], p1a, p1b, p1c, p1d, b2, b3);
            }
        }
        __syncthreads();

        if (t + 1 < NTILES) {
            load_v(t + 1);
            CP_COMMIT();
        }
    }

    rs0 += __shfl_xor_sync(0xffffffffu, rs0, 1);
    rs0 += __shfl_xor_sync(0xffffffffu, rs0, 2);
    rs1 += __shfl_xor_sync(0xffffffffu, rs1, 1);
    rs1 += __shfl_xor_sync(0xffffffffu, rs1, 2);
    float* sLp = (float*)(sm + SLP);
    if ((lane & 3) == 0) {
        sLp[half * 64 + ms + (lane >> 2)]     = rs0;
        sLp[half * 64 + ms + (lane >> 2) + 8] = rs1;
    }
    __syncthreads();

    float* ob = out + (size_t)b * C_IN * N_PIX + m_base;
#pragma unroll
    for (int mt = 0; mt < 2; ++mt) {
        int r0 = mw + mt * 16 + (lane >> 2);
        float inv0 = 1.0f / (sLp[r0] + sLp[64 + r0]);
        float inv1 = 1.0f / (sLp[r0 + 8] + sLp[64 + r0 + 8]);
#pragma unroll
        for (int j = 0; j < 8; ++j) {
            int c = cq + j * 8 + 2 * (lane & 3);
            ob[(size_t)c * N_PIX + r0]           = O[mt][j][0] * inv0;
            ob[(size_t)(c + 1) * N_PIX + r0]     = O[mt][j][1] * inv0;
            ob[(size_t)c * N_PIX + r0 + 8]       = O[mt][j][2] * inv1;
            ob[(size_t)(c + 1) * N_PIX + r0 + 8] = O[mt][j][3] * inv1;
        }
    }
}

// ---------------- launch ----------------
extern "C" void kernel_launch(void* const* d_in, const int* in_sizes, int n_in,
                              void* d_out, int out_size)
{
    const float* x1 = (const float*)d_in[0];
    const float* x2 = (const float*)d_in[1];

    fold_kernel<<<320, 256>>>(
        (const float*)d_in[2],  (const float*)d_in[3],  (const float*)d_in[4],
        (const float*)d_in[5],  (const float*)d_in[6],  (const float*)d_in[7],
        (const float*)d_in[8],  (const float*)d_in[9],  (const float*)d_in[10],
        (const float*)d_in[11], (const float*)d_in[12], (const float*)d_in[13],
        (const float*)d_in[14], (const float*)d_in[15], (const float*)d_in[16],
        (const float*)d_in[17], (const float*)d_in[18], (const float*)d_in[19]);

    proj2_kernel<<<dim3(N_PIX / 256, 10, B_SZ), 256>>>(x1, x2);

    cudaFuncSetAttribute(flash_mma, cudaFuncAttributeMaxDynamicSharedMemorySize, SMEM_TOTAL);
    flash_mma<<<dim3(N_PIX / M_TILE, B_SZ), 256, SMEM_TOTAL>>>((float*)d_out);
}